// round 3
// baseline (speedup 1.0000x reference)
#include <cuda_runtime.h>
#include <math.h>

#define NB 16
#define NC 128
#define NH 64
#define NW 64
#define NS 17            // 2*8+1 shifts per axis
#define NPOS 289         // 17*17
#define PLANE (NH*NW)    // 4096
#define CHW (NC*PLANE)   // 524288
#define CSPLIT 4
#define CPB (NC/CSPLIT)  // 32 channels per block

// Persistent device scratch (no allocations allowed).
__device__ float d_dot[NB*NB*NPOS];   // raw correlation sums
__device__ float d_part[NB*NPOS];     // raw window energy sums
__device__ float d_gsq[NB];           // ||grd_n||^2

// ---------------------------------------------------------------------------
// Zero the atomic accumulator (must be re-zeroed every launch).
__global__ void k_zero() {
    int i = blockIdx.x * blockDim.x + threadIdx.x;
    if (i < NB*NB*NPOS) d_dot[i] = 0.f;
}

// ---------------------------------------------------------------------------
// Per-grd-sample squared norm.
__global__ void k_gsq(const float* __restrict__ grd) {
    int n = blockIdx.x;
    const float* p = grd + (long long)n * CHW;
    float s = 0.f;
    for (int i = threadIdx.x; i < CHW; i += blockDim.x) {
        float v = p[i];
        s = fmaf(v, v, s);
    }
    __shared__ float r[32];
    for (int o = 16; o > 0; o >>= 1) s += __shfl_down_sync(0xffffffffu, s, o);
    int lane = threadIdx.x & 31, wid = threadIdx.x >> 5;
    if (lane == 0) r[wid] = s;
    __syncthreads();
    if (wid == 0) {
        s = (lane < (int)(blockDim.x >> 5)) ? r[lane] : 0.f;
        for (int o = 16; o > 0; o >>= 1) s += __shfl_down_sync(0xffffffffu, s, o);
        if (lane == 0) d_gsq[n] = s;
    }
}

// ---------------------------------------------------------------------------
// Raw window-energy sums: partical_raw[m,i,j] = sum over rows [i-8,i+56)∩[0,64),
// cols [j-8,j+56)∩[0,64) of sum_c sat[m,c,h,w]^2. Separable (cols then rows).
__global__ void k_part(const float* __restrict__ sat) {
    int m = blockIdx.x;
    __shared__ float e[PLANE];         // per-pixel channel-summed energy
    __shared__ float cw[NS * NH];      // [j][h] column-window sums
    const float* p = sat + (long long)m * CHW;
    for (int idx = threadIdx.x; idx < PLANE; idx += blockDim.x) {
        float s = 0.f;
        for (int c = 0; c < NC; c++) {
            float v = p[c * PLANE + idx];
            s = fmaf(v, v, s);
        }
        e[idx] = s;
    }
    __syncthreads();
    for (int t = threadIdx.x; t < NS * NH; t += blockDim.x) {
        int j = t / NH, h = t % NH;
        int lo = j - 8; if (lo < 0) lo = 0;
        int hi = j - 8 + 64; if (hi > NW) hi = NW;
        float s = 0.f;
        for (int w = lo; w < hi; w++) s += e[h * NW + w];
        cw[j * NH + h] = s;
    }
    __syncthreads();
    for (int t = threadIdx.x; t < NPOS; t += blockDim.x) {
        int i = t / NS, j = t % NS;
        int lo = i - 8; if (lo < 0) lo = 0;
        int hi = i - 8 + 64; if (hi > NH) hi = NH;
        float s = 0.f;
        for (int h = lo; h < hi; h++) s += cw[j * NH + h];
        d_part[m * NPOS + t] = s;
    }
}

// ---------------------------------------------------------------------------
// Main correlation: block = ((m,n) pair, channel quarter).
// Thread (di, hg): di in [0,17), 17 accumulators over dj, rows hg+16*hi.
// satp padded 80x81 (odd stride -> conflict-free shifted-row reads),
// gsh 64x65.
__global__ __launch_bounds__(272)
void k_corr(const float* __restrict__ sat, const float* __restrict__ grd) {
    __shared__ float satp[80 * 81];   // 6480 floats, zero border of 8
    __shared__ float gsh[64 * 65];    // 4160 floats

    int pair = blockIdx.x;
    int m = pair >> 4, n = pair & 15;
    int c0 = blockIdx.y * CPB;
    int t = threadIdx.x;
    int di = t >> 4;     // 0..16
    int hg = t & 15;     // 0..15

    for (int i = t; i < 80 * 81; i += 272) satp[i] = 0.f;

    float acc[NS];
#pragma unroll
    for (int k = 0; k < NS; k++) acc[k] = 0.f;

    const float* sbase = sat + (long long)(m * NC + c0) * PLANE;
    const float* gbase = grd + (long long)(n * NC + c0) * PLANE;

    for (int c = 0; c < CPB; c++) {
        __syncthreads();   // previous compute done / zeroing visible
        for (int idx = t; idx < PLANE; idx += 272) {
            int r = idx >> 6, w = idx & 63;
            satp[(r + 8) * 81 + (w + 8)] = sbase[c * PLANE + idx];
            gsh[r * 65 + w] = gbase[c * PLANE + idx];
        }
        __syncthreads();

#pragma unroll 1
        for (int hi = 0; hi < 4; hi++) {
            int h = hg + 16 * hi;
            const float* srow = &satp[(h + di) * 81];  // h+di in [0,80)
            const float* grow = &gsh[h * 65];
#pragma unroll 1
            for (int w0 = 0; w0 < 64; w0 += 16) {
                float s[32];
#pragma unroll
                for (int k = 0; k < 32; k++) s[k] = srow[w0 + k];
#pragma unroll
                for (int ww = 0; ww < 16; ww++) {
                    float gv = grow[w0 + ww];
#pragma unroll
                    for (int dj = 0; dj < NS; dj++)
                        acc[dj] = fmaf(gv, s[ww + dj], acc[dj]);
                }
            }
        }
    }

    __syncthreads();
    // Reduce over the 16 hg-partials via smem (reuse satp), then one atomic
    // per (di,dj) (only CSPLIT=4 colliders per address).
    float* red = satp;   // needs 272*17 = 4624 <= 6480
#pragma unroll
    for (int dj = 0; dj < NS; dj++) red[t * NS + dj] = acc[dj];
    __syncthreads();
    for (int q = t; q < NPOS; q += 272) {
        int qi = q / NS, qj = q % NS;
        float s = 0.f;
        for (int g = 0; g < 16; g++) s += red[(qi * 16 + g) * NS + qj];
        atomicAdd(&d_dot[pair * NPOS + q], s);
    }
}

// ---------------------------------------------------------------------------
__device__ __forceinline__ float softplusf(float x) {
    return fmaxf(x, 0.f) + log1pf(expf(-fabsf(x)));
}

// Finalize: sim -> dist -> loss terms. One block.
__global__ void k_final(float* __restrict__ out) {
    __shared__ float invp[NB * NPOS];
    __shared__ float gns[NB];
    __shared__ float dist[NB * NB];
    __shared__ float pos[NB];
    __shared__ float red[256];
    __shared__ float rowmin[NB];
    int t = threadIdx.x;

    for (int i = t; i < NB * NPOS; i += 256) invp[i] = rsqrtf(d_part[i]);
    if (t < NB) gns[t] = sqrtf(d_gsq[t]);
    __syncthreads();

    int m = t >> 4, n = t & 15;
    const float* dp = d_dot + t * NPOS;
    const float* ip = invp + m * NPOS;
    float best = -3.4e38f;
    for (int k = 0; k < NPOS; k++) best = fmaxf(best, dp[k] * ip[k]);
    float sim = best / gns[n];
    dist[t] = 2.f - 2.f * sim;
    __syncthreads();

    if (t < NB) pos[t] = dist[t * NB + t];
    __syncthreads();

    float x1 = (pos[n] - dist[t]) * 10.f;   // g2s: pos[None,:] - dist
    float x2 = (pos[m] - dist[t]) * 10.f;   // s2g: pos[:,None] - dist
    red[t] = softplusf(x1) + softplusf(x2);
    if (t < NB) {
        float mn = 3.4e38f;
        for (int k = 0; k < NB; k++) mn = fminf(mn, dist[t * NB + k]);
        rowmin[t] = mn;
    }
    __syncthreads();
    for (int s = 128; s > 0; s >>= 1) {
        if (t < s) red[t] += red[t + s];
        __syncthreads();
    }
    if (t == 0) {
        float pair_n = (float)(NB * (NB - 1));
        float loss = 10.f * (red[0] / (2.f * pair_n));
        float ps = 0.f, ms = 0.f;
        for (int k = 0; k < NB; k++) { ps += pos[k]; ms += rowmin[k]; }
        out[0] = loss;
        out[1] = ps / NB;
        out[2] = ms / NB;
    }
}

// ---------------------------------------------------------------------------
extern "C" void kernel_launch(void* const* d_in, const int* in_sizes, int n_in,
                              void* d_out, int out_size) {
    const float* sat = (const float*)d_in[0];
    const float* grd = (const float*)d_in[1];
    float* out = (float*)d_out;

    k_zero<<<(NB * NB * NPOS + 255) / 256, 256>>>();
    k_gsq<<<NB, 1024>>>(grd);
    k_part<<<NB, 1024>>>(sat);
    k_corr<<<dim3(NB * NB, CSPLIT), 272>>>(sat, grd);
    k_final<<<1, 256>>>(out);
}

// round 5
// speedup vs baseline: 7.2209x; 7.2209x over previous
#include <cuda_runtime.h>
#include <cuda_bf16.h>
#include <cstdint>
#include <math.h>

#define NB 16
#define NC 128
#define NH 64
#define NW 64
#define NS 17            // 2*8+1 shifts per axis
#define NPOS 289         // 17*17
#define PLANE (NH*NW)    // 4096
#define CHW (NC*PLANE)   // 524288

#define SW 82            // padded sat plane column stride (even -> aligned b32 pairs)
#define SROWS 84         // 64 + 16 shift + 2 spill rows for padded p-tiles (di<=18)
#define SPN (SROWS*SW)   // 6888 elements per copy
#define GS 520           // grd smem n-stride (word stride 260 -> conflict-free frags)
#define CSPL 16          // channel split (16 m x 16 splits = 256 blocks)
#define CPB (NC/CSPL)    // 8 channels per block

// Persistent device scratch (no allocations allowed).
__device__ float d_dot[NB*NB*NPOS];   // raw correlation sums
__device__ float d_part[NB*NPOS];     // raw window energy sums
__device__ float d_gsq[NB];           // ||grd_n||^2
__device__ float d_energy[NB*PLANE];  // per-pixel channel-summed sat energy

// ---------------------------------------------------------------------------
__global__ void k_zero() {
    int i = blockIdx.x * blockDim.x + threadIdx.x;
    if (i < NB*NB*NPOS) d_dot[i] = 0.f;
    if (i < NB*PLANE)   d_energy[i] = 0.f;
    if (i < NB)         d_gsq[i] = 0.f;
}

// ---------------------------------------------------------------------------
// ||grd_n||^2 with channel split for parallelism.
__global__ void k_gsq(const float* __restrict__ grd) {
    int n = blockIdx.x, cs = blockIdx.y;
    const float* p = grd + (size_t)n * CHW + (size_t)cs * (NC/8) * PLANE;
    float s = 0.f;
    for (int i = threadIdx.x; i < (NC/8) * PLANE; i += blockDim.x) {
        float v = p[i];
        s = fmaf(v, v, s);
    }
    __shared__ float r[32];
    for (int o = 16; o > 0; o >>= 1) s += __shfl_down_sync(0xffffffffu, s, o);
    int lane = threadIdx.x & 31, wid = threadIdx.x >> 5;
    if (lane == 0) r[wid] = s;
    __syncthreads();
    if (wid == 0) {
        s = (lane < (int)(blockDim.x >> 5)) ? r[lane] : 0.f;
        for (int o = 16; o > 0; o >>= 1) s += __shfl_down_sync(0xffffffffu, s, o);
        if (lane == 0) atomicAdd(&d_gsq[n], s);
    }
}

// ---------------------------------------------------------------------------
// Per-pixel channel-summed sat energy, channel-split, atomic-accumulated.
__global__ void k_energy(const float* __restrict__ sat) {
    int m = blockIdx.x, cs = blockIdx.y;
    const float* p = sat + (size_t)m * CHW + (size_t)cs * (NC/8) * PLANE;
    for (int idx = threadIdx.x; idx < PLANE; idx += blockDim.x) {
        float s = 0.f;
        for (int c = 0; c < NC/8; c++) {
            float v = p[c * PLANE + idx];
            s = fmaf(v, v, s);
        }
        atomicAdd(&d_energy[m * PLANE + idx], s);
    }
}

// ---------------------------------------------------------------------------
// Separable window sums from d_energy (cheap, 16 blocks).
__global__ void k_part2() {
    int m = blockIdx.x;
    __shared__ float e[PLANE];
    __shared__ float cw[NS * NH];
    for (int i = threadIdx.x; i < PLANE; i += blockDim.x)
        e[i] = d_energy[m * PLANE + i];
    __syncthreads();
    for (int t = threadIdx.x; t < NS * NH; t += blockDim.x) {
        int j = t / NH, h = t % NH;
        int lo = j - 8; if (lo < 0) lo = 0;
        int hi = j - 8 + 64; if (hi > NW) hi = NW;
        float s = 0.f;
        for (int w = lo; w < hi; w++) s += e[h * NW + w];
        cw[j * NH + h] = s;
    }
    __syncthreads();
    for (int t = threadIdx.x; t < NPOS; t += blockDim.x) {
        int i = t / NS, j = t % NS;
        int lo = i - 8; if (lo < 0) lo = 0;
        int hi = i - 8 + 64; if (hi > NH) hi = NH;
        float s = 0.f;
        for (int h = lo; h < hi; h++) s += cw[j * NH + h];
        d_part[m * NPOS + t] = s;
    }
}

// ---------------------------------------------------------------------------
__device__ __forceinline__ void mma16816(float* c,
    unsigned int a0, unsigned int a1, unsigned int a2, unsigned int a3,
    unsigned int b0, unsigned int b1) {
    asm volatile(
        "mma.sync.aligned.m16n8k16.row.col.f32.bf16.bf16.f32 "
        "{%0,%1,%2,%3}, {%4,%5,%6,%7}, {%8,%9}, {%0,%1,%2,%3};"
        : "+f"(c[0]), "+f"(c[1]), "+f"(c[2]), "+f"(c[3])
        : "r"(a0), "r"(a1), "r"(a2), "r"(a3), "r"(b0), "r"(b1));
}

// Main correlation on tensor cores.
// Block = (m, channel-split of 8 channels). 256 threads = 8 warps.
// GEMM: C[n=16, p=shift] = sum_k grd[n,k] * satshift[k,p], K tiled by
// (channel, 8-row band, 16-wide w chunk). A = grd fragment (shared across
// p-tiles), B = computed-address loads from dual-parity padded bf16 sat plane.
// Warp w owns p in [w*40, w*40+40): 5 n8-tiles; p>=289 padded (zero sat rows).
__global__ __launch_bounds__(256, 2)
void k_corr_mma(const float* __restrict__ sat, const float* __restrict__ grd) {
    __shared__ __align__(16) __nv_bfloat16 sp[2 * SPN];   // [0]=even copy, [SPN]=shift-by-1 copy
    __shared__ __align__(16) __nv_bfloat16 gsh[16 * GS];  // grd band [n][8*64], stride GS

    int m = blockIdx.x;
    int c0 = blockIdx.y * CPB;
    int t = threadIdx.x;
    int lane = t & 31, warp = t >> 5;
    int tig = lane & 3, grp = lane >> 2;

    // Zero both sat copies once (borders + spill rows stay zero forever).
    for (int i = t; i < 2 * SPN; i += 256) sp[i] = __float2bfloat16(0.f);

    // Per-thread, per-tile B-fragment base offsets (constant over K loop).
    int boff[5];
#pragma unroll
    for (int tt = 0; tt < 5; tt++) {
        int p = warp * 40 + tt * 8 + grp;        // B-frag column = groupID
        int di = p / 17, dj = p % 17;            // p<=319 -> di<=18 (zero spill rows)
        boff[tt] = (dj & 1) * SPN + di * SW + (dj & ~1) + tig * 2;
    }

    float acc[5][4];
#pragma unroll
    for (int tt = 0; tt < 5; tt++)
#pragma unroll
        for (int k = 0; k < 4; k++) acc[tt][k] = 0.f;

    const float* sb = sat + (size_t)(m * NC + c0) * PLANE;

    for (int c = 0; c < CPB; c++) {
        __syncthreads();   // previous channel's compute done before satp overwrite
        // Load sat plane -> bf16, interior at (row+8, col+8); odd copy shifted left 1.
        for (int i = t; i < PLANE / 2; i += 256) {
            int r = i >> 5;       // row 0..63
            int wp = i & 31;      // pair of cols 2wp, 2wp+1
            float2 v = *(const float2*)(sb + c * PLANE + r * 64 + wp * 2);
            __nv_bfloat162 bv = __floats2bfloat162_rn(v.x, v.y);
            *(__nv_bfloat162*)&sp[(r + 8) * SW + wp * 2 + 8] = bv;   // even index
            sp[SPN + (r + 8) * SW + wp * 2 + 7] = bv.x;  // sp_o[c-1] = val[c]
            sp[SPN + (r + 8) * SW + wp * 2 + 8] = bv.y;
        }

        for (int b = 0; b < 8; b++) {
            __syncthreads();   // prev band compute done; also orders satp stores (b==0)
            // Load grd band: 16 n x 8 rows x 64 w -> bf16, n-stride GS.
            for (int e = t; e < 4096; e += 256) {
                int n = e >> 8, rem = e & 255;
                const float* gp = grd + (size_t)(n * NC + c0 + c) * PLANE + b * 512 + rem * 2;
                float2 v = *(const float2*)gp;
                *(__nv_bfloat162*)&gsh[n * GS + rem * 2] = __floats2bfloat162_rn(v.x, v.y);
            }
            __syncthreads();

            int hb = b * 8;
#pragma unroll 1
            for (int hh = 0; hh < 8; hh++) {
                int coff = (hb + hh) * SW;                 // sat row offset
                int ab = grp * GS + hh * 64 + tig * 2;     // grd frag base
#pragma unroll
                for (int w0 = 0; w0 < 64; w0 += 16) {
                    // A fragment: rows grp/grp+8 (n), k = tig*2..+1, +8..+9
                    unsigned int a0 = *(const unsigned int*)&gsh[ab + w0];
                    unsigned int a1 = *(const unsigned int*)&gsh[ab + w0 + 8 * GS];
                    unsigned int a2 = *(const unsigned int*)&gsh[ab + w0 + 8];
                    unsigned int a3 = *(const unsigned int*)&gsh[ab + w0 + 8 * GS + 8];
#pragma unroll
                    for (int tt = 0; tt < 5; tt++) {
                        const __nv_bfloat16* bp = &sp[boff[tt] + coff + w0];
                        unsigned int b0 = *(const unsigned int*)bp;
                        unsigned int b1 = *(const unsigned int*)(bp + 8);
                        mma16816(acc[tt], a0, a1, a2, a3, b0, b1);
                    }
                }
            }
        }
    }

    // C layout: c0=C[grp][tig*2], c1=[grp][tig*2+1], c2=[grp+8][tig*2], c3=[grp+8][tig*2+1]
#pragma unroll
    for (int tt = 0; tt < 5; tt++) {
        int p0 = warp * 40 + tt * 8 + tig * 2;
        if (p0 < NPOS) {
            atomicAdd(&d_dot[(m * 16 + grp) * NPOS + p0],     acc[tt][0]);
            atomicAdd(&d_dot[(m * 16 + grp + 8) * NPOS + p0], acc[tt][2]);
            if (p0 + 1 < NPOS) {
                atomicAdd(&d_dot[(m * 16 + grp) * NPOS + p0 + 1],     acc[tt][1]);
                atomicAdd(&d_dot[(m * 16 + grp + 8) * NPOS + p0 + 1], acc[tt][3]);
            }
        }
    }
}

// ---------------------------------------------------------------------------
__device__ __forceinline__ float softplusf(float x) {
    return fmaxf(x, 0.f) + log1pf(expf(-fabsf(x)));
}

// Finalize: sim -> dist -> loss terms. One block.
__global__ void k_final(float* __restrict__ out) {
    __shared__ float invp[NB * NPOS];
    __shared__ float gns[NB];
    __shared__ float dist[NB * NB];
    __shared__ float pos[NB];
    __shared__ float red[256];
    __shared__ float rowmin[NB];
    int t = threadIdx.x;

    for (int i = t; i < NB * NPOS; i += 256) invp[i] = rsqrtf(d_part[i]);
    if (t < NB) gns[t] = sqrtf(d_gsq[t]);
    __syncthreads();

    int m = t >> 4, n = t & 15;
    const float* dp = d_dot + t * NPOS;
    const float* ip = invp + m * NPOS;
    float best = -3.4e38f;
    for (int k = 0; k < NPOS; k++) best = fmaxf(best, dp[k] * ip[k]);
    float sim = best / gns[n];
    dist[t] = 2.f - 2.f * sim;
    __syncthreads();

    if (t < NB) pos[t] = dist[t * NB + t];
    __syncthreads();

    float x1 = (pos[n] - dist[t]) * 10.f;   // g2s: pos[None,:] - dist
    float x2 = (pos[m] - dist[t]) * 10.f;   // s2g: pos[:,None] - dist
    red[t] = softplusf(x1) + softplusf(x2);
    if (t < NB) {
        float mn = 3.4e38f;
        for (int k = 0; k < NB; k++) mn = fminf(mn, dist[t * NB + k]);
        rowmin[t] = mn;
    }
    __syncthreads();
    for (int s = 128; s > 0; s >>= 1) {
        if (t < s) red[t] += red[t + s];
        __syncthreads();
    }
    if (t == 0) {
        float pair_n = (float)(NB * (NB - 1));
        float loss = 10.f * (red[0] / (2.f * pair_n));
        float ps = 0.f, ms = 0.f;
        for (int k = 0; k < NB; k++) { ps += pos[k]; ms += rowmin[k]; }
        out[0] = loss;
        out[1] = ps / NB;
        out[2] = ms / NB;
    }
}

// ---------------------------------------------------------------------------
extern "C" void kernel_launch(void* const* d_in, const int* in_sizes, int n_in,
                              void* d_out, int out_size) {
    const float* sat = (const float*)d_in[0];
    const float* grd = (const float*)d_in[1];
    float* out = (float*)d_out;

    k_zero<<<(NB * NB * NPOS + 255) / 256, 256>>>();
    k_gsq<<<dim3(NB, 8), 256>>>(grd);
    k_energy<<<dim3(NB, 8), 256>>>(sat);
    k_part2<<<NB, 256>>>();
    k_corr_mma<<<dim3(NB, CSPL), 256>>>(sat, grd);
    k_final<<<1, 256>>>(out);
}

// round 8
// speedup vs baseline: 7.3288x; 1.0149x over previous
#include <cuda_runtime.h>
#include <cuda_bf16.h>
#include <cstdint>
#include <math.h>

#define NB 16
#define NC 128
#define NH 64
#define NW 64
#define NS 17            // 2*8+1 shifts per axis
#define NPOS 289         // 17*17
#define PLANE (NH*NW)    // 4096
#define CHW (NC*PLANE)   // 524288

#define SW 82            // padded sat plane column stride (even -> aligned b32 pairs)
#define SROWS 84         // 64 + 16 shift + 2 spill rows for padded p-tiles (di<=18)
#define SPN (SROWS*SW)   // 6888 elements per copy
#define GS 520           // grd smem n-stride (word stride 260; 8-mult -> 16B-aligned ldmatrix rows)
#define CSPL 16          // channel split (16 m x 16 splits = 256 blocks)
#define CPB (NC/CSPL)    // 8 channels per block

// Persistent device scratch (no allocations allowed).
__device__ float d_dot[NB*NB*NPOS];   // raw correlation sums
__device__ float d_part[NB*NPOS];     // raw window energy sums
__device__ float d_gsq[NB];           // ||grd_n||^2
__device__ float d_energy[NB*PLANE];  // per-pixel channel-summed sat energy

// ---------------------------------------------------------------------------
__global__ void k_zero() {
    int i = blockIdx.x * blockDim.x + threadIdx.x;
    if (i < NB*NB*NPOS) d_dot[i] = 0.f;
    if (i < NB*PLANE)   d_energy[i] = 0.f;
    if (i < NB)         d_gsq[i] = 0.f;
}

// ---------------------------------------------------------------------------
// ||grd_n||^2 with channel split for parallelism.
__global__ void k_gsq(const float* __restrict__ grd) {
    int n = blockIdx.x, cs = blockIdx.y;
    const float4* p = (const float4*)(grd + (size_t)n * CHW + (size_t)cs * (NC/8) * PLANE);
    float s = 0.f;
    for (int i = threadIdx.x; i < (NC/8) * PLANE / 4; i += blockDim.x) {
        float4 v = p[i];
        s = fmaf(v.x, v.x, s); s = fmaf(v.y, v.y, s);
        s = fmaf(v.z, v.z, s); s = fmaf(v.w, v.w, s);
    }
    __shared__ float r[32];
    for (int o = 16; o > 0; o >>= 1) s += __shfl_down_sync(0xffffffffu, s, o);
    int lane = threadIdx.x & 31, wid = threadIdx.x >> 5;
    if (lane == 0) r[wid] = s;
    __syncthreads();
    if (wid == 0) {
        s = (lane < (int)(blockDim.x >> 5)) ? r[lane] : 0.f;
        for (int o = 16; o > 0; o >>= 1) s += __shfl_down_sync(0xffffffffu, s, o);
        if (lane == 0) atomicAdd(&d_gsq[n], s);
    }
}

// ---------------------------------------------------------------------------
// Per-pixel channel-summed sat energy, channel-split, atomic-accumulated.
__global__ void k_energy(const float* __restrict__ sat) {
    int m = blockIdx.x, cs = blockIdx.y;
    const float* p = sat + (size_t)m * CHW + (size_t)cs * (NC/8) * PLANE;
    for (int idx = threadIdx.x; idx < PLANE; idx += blockDim.x) {
        float s = 0.f;
        for (int c = 0; c < NC/8; c++) {
            float v = p[c * PLANE + idx];
            s = fmaf(v, v, s);
        }
        atomicAdd(&d_energy[m * PLANE + idx], s);
    }
}

// ---------------------------------------------------------------------------
// Separable window sums from d_energy (cheap; wide blocks for latency).
__global__ void k_part2() {
    int m = blockIdx.x;
    __shared__ float e[PLANE];
    __shared__ float cw[NS * NH];
    for (int i = threadIdx.x; i < PLANE; i += blockDim.x)
        e[i] = d_energy[m * PLANE + i];
    __syncthreads();
    for (int t = threadIdx.x; t < NS * NH; t += blockDim.x) {
        int j = t / NH, h = t % NH;
        int lo = j - 8; if (lo < 0) lo = 0;
        int hi = j - 8 + 64; if (hi > NW) hi = NW;
        float s = 0.f;
        for (int w = lo; w < hi; w++) s += e[h * NW + w];
        cw[j * NH + h] = s;
    }
    __syncthreads();
    for (int t = threadIdx.x; t < NPOS; t += blockDim.x) {
        int i = t / NS, j = t % NS;
        int lo = i - 8; if (lo < 0) lo = 0;
        int hi = i - 8 + 64; if (hi > NH) hi = NH;
        float s = 0.f;
        for (int h = lo; h < hi; h++) s += cw[j * NH + h];
        d_part[m * NPOS + t] = s;
    }
}

// ---------------------------------------------------------------------------
__device__ __forceinline__ void mma16816(float* c,
    unsigned int a0, unsigned int a1, unsigned int a2, unsigned int a3,
    unsigned int b0, unsigned int b1) {
    asm volatile(
        "mma.sync.aligned.m16n8k16.row.col.f32.bf16.bf16.f32 "
        "{%0,%1,%2,%3}, {%4,%5,%6,%7}, {%8,%9}, {%0,%1,%2,%3};"
        : "+f"(c[0]), "+f"(c[1]), "+f"(c[2]), "+f"(c[3])
        : "r"(a0), "r"(a1), "r"(a2), "r"(a3), "r"(b0), "r"(b1));
}

__device__ __forceinline__ void ldsm_x4(unsigned int& a0, unsigned int& a1,
                                        unsigned int& a2, unsigned int& a3,
                                        unsigned int saddr) {
    asm volatile("ldmatrix.sync.aligned.m8n8.x4.shared.b16 {%0,%1,%2,%3}, [%4];"
        : "=r"(a0), "=r"(a1), "=r"(a2), "=r"(a3) : "r"(saddr));
}

// Main correlation on tensor cores.
// Block = (m, channel-split of 8 channels). 256 threads = 8 warps.
// GEMM: C[n=16, p=shift] = sum_k grd[n,k] * satshift[k,p], K tiled by
// (channel, 8-row band, 16-wide w chunk). A = grd fragment via one
// ldmatrix.x4 (shared across p-tiles), B = computed-address LDS from
// dual-parity padded bf16 sat plane.
// Warp w owns p in [w*40, w*40+40): 5 n8-tiles; p>=289 padded (zero sat rows).
__global__ __launch_bounds__(256, 2)
void k_corr_mma(const float* __restrict__ sat, const float* __restrict__ grd) {
    __shared__ __align__(16) __nv_bfloat16 sp[2 * SPN];   // [0]=even copy, [SPN]=shift-by-1 copy
    __shared__ __align__(16) __nv_bfloat16 gsh[16 * GS];  // grd band [n][8*64], stride GS

    int m = blockIdx.x;
    int c0 = blockIdx.y * CPB;
    int t = threadIdx.x;
    int lane = t & 31, warp = t >> 5;
    int tig = lane & 3, grp = lane >> 2;

    // Zero both sat copies once (borders + spill rows stay zero forever).
    for (int i = t; i < 2 * SPN; i += 256) sp[i] = __float2bfloat16(0.f);

    // Per-thread, per-tile B-fragment base offsets (constant over K loop).
    int boff[5];
#pragma unroll
    for (int tt = 0; tt < 5; tt++) {
        int p = warp * 40 + tt * 8 + grp;        // B-frag column = groupID
        int di = p / 17, dj = p % 17;            // p<=319 -> di<=18 (zero spill rows)
        boff[tt] = (dj & 1) * SPN + di * SW + (dj & ~1) + tig * 2;
    }

    // ldmatrix A address role: lanes 0-7 -> rows n=0..7 k-low, 8-15 -> n=8..15
    // k-low, 16-23 -> n=0..7 k-high, 24-31 -> n=8..15 k-high.
    unsigned int gbase = (unsigned int)__cvta_generic_to_shared(gsh);
    int arow = (lane & 7) + ((lane >> 3) & 1) * 8;
    int akhi = (lane & 16) ? 8 : 0;
    unsigned int abase = gbase + (unsigned int)(arow * GS + akhi) * 2u;

    float acc[5][4];
#pragma unroll
    for (int tt = 0; tt < 5; tt++)
#pragma unroll
        for (int k = 0; k < 4; k++) acc[tt][k] = 0.f;

    const float* sb = sat + (size_t)(m * NC + c0) * PLANE;

    for (int c = 0; c < CPB; c++) {
        __syncthreads();   // previous channel's compute done before satp overwrite
        // Load sat plane -> bf16, interior at (row+8, col+8); odd copy shifted left 1.
        for (int i = t; i < PLANE / 2; i += 256) {
            int r = i >> 5;       // row 0..63
            int wp = i & 31;      // pair of cols 2wp, 2wp+1
            float2 v = *(const float2*)(sb + c * PLANE + r * 64 + wp * 2);
            __nv_bfloat162 bv = __floats2bfloat162_rn(v.x, v.y);
            *(__nv_bfloat162*)&sp[(r + 8) * SW + wp * 2 + 8] = bv;   // even index
            sp[SPN + (r + 8) * SW + wp * 2 + 7] = bv.x;  // sp_o[c-1] = val[c]
            sp[SPN + (r + 8) * SW + wp * 2 + 8] = bv.y;
        }

        for (int b = 0; b < 8; b++) {
            __syncthreads();   // prev band compute done; also orders satp stores (b==0)
            // Load grd band: 16 n x 8 rows x 64 w -> bf16, n-stride GS.
            for (int e = t; e < 4096; e += 256) {
                int n = e >> 8, rem = e & 255;
                const float* gp = grd + (size_t)(n * NC + c0 + c) * PLANE + b * 512 + rem * 2;
                float2 v = *(const float2*)gp;
                *(__nv_bfloat162*)&gsh[n * GS + rem * 2] = __floats2bfloat162_rn(v.x, v.y);
            }
            __syncthreads();

            int hb = b * 8;
#pragma unroll 2
            for (int hh = 0; hh < 8; hh++) {
                int coff = (hb + hh) * SW;                 // sat row offset
                unsigned int arowaddr = abase + (unsigned int)(hh * 64) * 2u;
#pragma unroll
                for (int w0 = 0; w0 < 64; w0 += 16) {
                    unsigned int a0, a1, a2, a3;
                    ldsm_x4(a0, a1, a2, a3, arowaddr + (unsigned int)w0 * 2u);
#pragma unroll
                    for (int tt = 0; tt < 5; tt++) {
                        const __nv_bfloat16* bp = &sp[boff[tt] + coff + w0];
                        unsigned int b0 = *(const unsigned int*)bp;
                        unsigned int b1 = *(const unsigned int*)(bp + 8);
                        mma16816(acc[tt], a0, a1, a2, a3, b0, b1);
                    }
                }
            }
        }
    }

    // C layout: c0=C[grp][tig*2], c1=[grp][tig*2+1], c2=[grp+8][tig*2], c3=[grp+8][tig*2+1]
#pragma unroll
    for (int tt = 0; tt < 5; tt++) {
        int p0 = warp * 40 + tt * 8 + tig * 2;
        if (p0 < NPOS) {
            atomicAdd(&d_dot[(m * 16 + grp) * NPOS + p0],     acc[tt][0]);
            atomicAdd(&d_dot[(m * 16 + grp + 8) * NPOS + p0], acc[tt][2]);
            if (p0 + 1 < NPOS) {
                atomicAdd(&d_dot[(m * 16 + grp) * NPOS + p0 + 1],     acc[tt][1]);
                atomicAdd(&d_dot[(m * 16 + grp + 8) * NPOS + p0 + 1], acc[tt][3]);
            }
        }
    }
}

// ---------------------------------------------------------------------------
__device__ __forceinline__ float softplusf(float x) {
    return fmaxf(x, 0.f) + log1pf(expf(-fabsf(x)));
}

// Finalize: sim -> dist -> loss terms. One block.
__global__ void k_final(float* __restrict__ out) {
    __shared__ float invp[NB * NPOS];
    __shared__ float gns[NB];
    __shared__ float dist[NB * NB];
    __shared__ float pos[NB];
    __shared__ float red[256];
    __shared__ float rowmin[NB];
    int t = threadIdx.x;

    for (int i = t; i < NB * NPOS; i += 256) invp[i] = rsqrtf(d_part[i]);
    if (t < NB) gns[t] = sqrtf(d_gsq[t]);
    __syncthreads();

    int m = t >> 4, n = t & 15;
    const float* dp = d_dot + t * NPOS;
    const float* ip = invp + m * NPOS;
    float best = -3.4e38f;
    for (int k = 0; k < NPOS; k++) best = fmaxf(best, dp[k] * ip[k]);
    float sim = best / gns[n];
    dist[t] = 2.f - 2.f * sim;
    __syncthreads();

    if (t < NB) pos[t] = dist[t * NB + t];
    __syncthreads();

    float x1 = (pos[n] - dist[t]) * 10.f;   // g2s: pos[None,:] - dist
    float x2 = (pos[m] - dist[t]) * 10.f;   // s2g: pos[:,None] - dist
    red[t] = softplusf(x1) + softplusf(x2);
    if (t < NB) {
        float mn = 3.4e38f;
        for (int k = 0; k < NB; k++) mn = fminf(mn, dist[t * NB + k]);
        rowmin[t] = mn;
    }
    __syncthreads();
    for (int s = 128; s > 0; s >>= 1) {
        if (t < s) red[t] += red[t + s];
        __syncthreads();
    }
    if (t == 0) {
        float pair_n = (float)(NB * (NB - 1));
        float loss = 10.f * (red[0] / (2.f * pair_n));
        float ps = 0.f, ms = 0.f;
        for (int k = 0; k < NB; k++) { ps += pos[k]; ms += rowmin[k]; }
        out[0] = loss;
        out[1] = ps / NB;
        out[2] = ms / NB;
    }
}

// ---------------------------------------------------------------------------
extern "C" void kernel_launch(void* const* d_in, const int* in_sizes, int n_in,
                              void* d_out, int out_size) {
    const float* sat = (const float*)d_in[0];
    const float* grd = (const float*)d_in[1];
    float* out = (float*)d_out;

    // NOTE: k_corr_mma deliberately placed at the launch slot the ncu capture
    // profiled last round (was k_part2), so next profile shows the hot kernel.
    k_zero<<<(NB * NB * NPOS + 255) / 256, 256>>>();
    k_gsq<<<dim3(NB, 8), 256>>>(grd);
    k_energy<<<dim3(NB, 8), 256>>>(sat);
    k_corr_mma<<<dim3(NB, CSPL), 256>>>(sat, grd);
    k_part2<<<NB, 1024>>>();
    k_final<<<1, 256>>>(out);
}

// round 9
// speedup vs baseline: 7.7874x; 1.0626x over previous
#include <cuda_runtime.h>
#include <cuda_bf16.h>
#include <cstdint>
#include <math.h>

#define NB 16
#define NC 128
#define NH 64
#define NW 64
#define NS 17            // 2*8+1 shifts per axis
#define NPOS 289         // 17*17
#define PLANE (NH*NW)    // 4096
#define CHW (NC*PLANE)   // 524288

#define SW 82            // padded sat plane column stride
#define SROWS 84         // 64 + 16 shift + 2 spill rows (di<=18); SPN/2 mod 32 = 20 -> parity copies conflict-free
#define SPN (SROWS*SW)   // 6888 elements per copy
#define GSE 264          // grd smem n-stride elems (264*2=528B, 16B-aligned; 132 words mod 32 = 4 -> ldsm conflict-free)
#define BUFE (16*GSE)    // one grd band buffer (16 n x 256 k)
#define CSPL 16          // channel split (16 m x 16 splits = 256 blocks)
#define CPB (NC/CSPL)    // 8 channels per block
#define NBANDS (CPB*16)  // 128 4-row bands per block

// Persistent device scratch (no allocations allowed).
__device__ float d_dot[NB*NB*NPOS];            // raw correlation sums
__device__ float d_part[NB*NPOS];              // raw window energy sums
__device__ float d_gsq[NB];                    // ||grd_n||^2
__device__ float d_energy[NB*PLANE];           // per-pixel channel-summed sat energy
__device__ __nv_bfloat16 d_satb[NB*CHW];       // bf16 copy of sat
__device__ __nv_bfloat16 d_grdb[NB*CHW];       // bf16 copy of grd

// ---------------------------------------------------------------------------
__global__ void k_zero() {
    int i = blockIdx.x * blockDim.x + threadIdx.x;
    if (i < NB*NB*NPOS) d_dot[i] = 0.f;
    if (i < NB*PLANE)   d_energy[i] = 0.f;
    if (i < NB)         d_gsq[i] = 0.f;
}

// ---------------------------------------------------------------------------
// grd: fp32 -> bf16 conversion fused with ||grd_n||^2 reduction.
__global__ void k_prep_grd(const float* __restrict__ grd) {
    int n = blockIdx.x, cs = blockIdx.y;   // 8 channel splits
    size_t base = (size_t)n * CHW + (size_t)cs * (CHW/8);
    const float4* src = (const float4*)(grd + base);
    uint2* dst = (uint2*)(d_grdb + base);
    float s = 0.f;
    for (int i = threadIdx.x; i < CHW/8/4; i += blockDim.x) {
        float4 v = src[i];
        s = fmaf(v.x, v.x, s); s = fmaf(v.y, v.y, s);
        s = fmaf(v.z, v.z, s); s = fmaf(v.w, v.w, s);
        __nv_bfloat162 lo = __floats2bfloat162_rn(v.x, v.y);
        __nv_bfloat162 hi = __floats2bfloat162_rn(v.z, v.w);
        uint2 o;
        o.x = *(unsigned*)&lo; o.y = *(unsigned*)&hi;
        dst[i] = o;
    }
    __shared__ float r[32];
    for (int o = 16; o > 0; o >>= 1) s += __shfl_down_sync(0xffffffffu, s, o);
    int lane = threadIdx.x & 31, wid = threadIdx.x >> 5;
    if (lane == 0) r[wid] = s;
    __syncthreads();
    if (wid == 0) {
        s = (lane < (int)(blockDim.x >> 5)) ? r[lane] : 0.f;
        for (int o = 16; o > 0; o >>= 1) s += __shfl_down_sync(0xffffffffu, s, o);
        if (lane == 0) atomicAdd(&d_gsq[n], s);
    }
}

// ---------------------------------------------------------------------------
// sat: fp32 -> bf16 conversion fused with per-pixel channel energy.
__global__ void k_prep_sat(const float* __restrict__ sat) {
    int m = blockIdx.x, cs = blockIdx.y;      // 8 splits x 16 channels
    size_t base = (size_t)(m*NC + cs*16) * PLANE;
    const float* p = sat + base;
    __nv_bfloat16* q = d_satb + base;
    for (int idx = threadIdx.x; idx < PLANE; idx += blockDim.x) {
        float s = 0.f;
        for (int c = 0; c < 16; c++) {
            float v = p[c*PLANE + idx];
            s = fmaf(v, v, s);
            q[c*PLANE + idx] = __float2bfloat16(v);
        }
        atomicAdd(&d_energy[m*PLANE + idx], s);
    }
}

// ---------------------------------------------------------------------------
// Separable window sums from d_energy.
__global__ void k_part2() {
    int m = blockIdx.x;
    __shared__ float e[PLANE];
    __shared__ float cw[NS * NH];
    for (int i = threadIdx.x; i < PLANE; i += blockDim.x)
        e[i] = d_energy[m * PLANE + i];
    __syncthreads();
    for (int t = threadIdx.x; t < NS * NH; t += blockDim.x) {
        int j = t / NH, h = t % NH;
        int lo = j - 8; if (lo < 0) lo = 0;
        int hi = j - 8 + 64; if (hi > NW) hi = NW;
        float s = 0.f;
        for (int w = lo; w < hi; w++) s += e[h * NW + w];
        cw[j * NH + h] = s;
    }
    __syncthreads();
    for (int t = threadIdx.x; t < NPOS; t += blockDim.x) {
        int i = t / NS, j = t % NS;
        int lo = i - 8; if (lo < 0) lo = 0;
        int hi = i - 8 + 64; if (hi > NH) hi = NH;
        float s = 0.f;
        for (int h = lo; h < hi; h++) s += cw[j * NH + h];
        d_part[m * NPOS + t] = s;
    }
}

// ---------------------------------------------------------------------------
__device__ __forceinline__ void mma16816(float* c,
    unsigned a0, unsigned a1, unsigned a2, unsigned a3,
    unsigned b0, unsigned b1) {
    asm volatile(
        "mma.sync.aligned.m16n8k16.row.col.f32.bf16.bf16.f32 "
        "{%0,%1,%2,%3}, {%4,%5,%6,%7}, {%8,%9}, {%0,%1,%2,%3};"
        : "+f"(c[0]), "+f"(c[1]), "+f"(c[2]), "+f"(c[3])
        : "r"(a0), "r"(a1), "r"(a2), "r"(a3), "r"(b0), "r"(b1));
}

__device__ __forceinline__ void ldsm_x4(unsigned& a0, unsigned& a1,
                                        unsigned& a2, unsigned& a3,
                                        unsigned saddr) {
    asm volatile("ldmatrix.sync.aligned.m8n8.x4.shared.b16 {%0,%1,%2,%3}, [%4];"
        : "=r"(a0), "=r"(a1), "=r"(a2), "=r"(a3) : "r"(saddr));
}

__device__ __forceinline__ void cpasync16(unsigned dst, const void* src) {
    asm volatile("cp.async.ca.shared.global [%0], [%1], 16;" :: "r"(dst), "l"(src));
}
#define CP_COMMIT() asm volatile("cp.async.commit_group;")
#define CP_WAIT1()  asm volatile("cp.async.wait_group 1;")
#define CP_WAIT0()  asm volatile("cp.async.wait_group 0;")

// ---------------------------------------------------------------------------
// Main correlation on tensor cores.
// Block = (m, channel-split of 8 channels). 256 threads = 8 warps.
// C[n=16, p=320] = sum_k grd[n,k]*satshift[k,p]. K tiled by 128 4-row bands.
// grd bands double-buffered via cp.async (bf16 source, no conversion).
// Inner loop software-pipelined one step (ldsm + 10 B-LDS) ahead of 5 mmas.
__global__ __launch_bounds__(256, 2)
void k_corr_mma(const float* __restrict__ satf, const float* __restrict__ grdf) {
    __shared__ __align__(16) __nv_bfloat16 sp[2 * SPN];   // dual-parity sat copies
    __shared__ __align__(16) __nv_bfloat16 gsh[2 * BUFE]; // double-buffered grd band

    int m = blockIdx.x;
    int c0 = blockIdx.y * CPB;
    int t = threadIdx.x;
    int lane = t & 31, warp = t >> 5;
    int tig = lane & 3, grp = lane >> 2;

    // Zero both sat copies once (borders + spill rows stay zero forever).
    for (int i = t; i < 2 * SPN; i += 256) sp[i] = __float2bfloat16(0.f);

    // Per-thread, per-tile B-fragment base offsets (constant over K loop).
    int boff[5];
#pragma unroll
    for (int tt = 0; tt < 5; tt++) {
        int p = warp * 40 + tt * 8 + grp;        // B-frag column = groupID
        int di = p / 17, dj = p % 17;            // p<=319 -> di<=18 (zero spill rows)
        boff[tt] = (dj & 1) * SPN + di * SW + (dj & ~1) + tig * 2;
    }

    // ldmatrix A lane roles (validated R8 mapping).
    unsigned gshb = (unsigned)__cvta_generic_to_shared(gsh);
    int arow = (lane & 7) + ((lane >> 3) & 1) * 8;
    int akhi = (lane & 16) ? 8 : 0;
    unsigned aoff = (unsigned)(arow * GSE + akhi);

    float acc[5][4];
#pragma unroll
    for (int tt = 0; tt < 5; tt++)
#pragma unroll
        for (int k = 0; k < 4; k++) acc[tt][k] = 0.f;

    // ---- cp.async copy of one grd band (16 n x 256 bf16) ----
    auto issue_copy = [&](int tb) {
        int buf = tb & 1;
        int c = c0 + (tb >> 4), bb = tb & 15;
#pragma unroll
        for (int i = 0; i < 2; i++) {
            int q = t + i * 256;
            int n = q >> 5, ch = q & 31;
            const __nv_bfloat16* src =
                d_grdb + ((size_t)(m*0 + n*NC + c) * PLANE) + (bb << 8) + (ch << 3);
            unsigned dst = gshb + ((unsigned)buf*BUFE + (unsigned)(n*GSE) + (unsigned)(ch<<3)) * 2u;
            cpasync16(dst, src);
        }
    };

    // prologue: band 0 in flight
    issue_copy(0);
    CP_COMMIT();

    for (int tb = 0; tb < NBANDS; tb++) {
        __syncthreads();   // all warps done with previous band / satp reads
        if (tb + 1 < NBANDS) { issue_copy(tb + 1); CP_COMMIT(); }
        if ((tb & 15) == 0) {
            // load sat plane for channel tb>>4 (bf16 source), dual parity
            const __nv_bfloat16* sb = d_satb + (size_t)(m*NC + c0 + (tb >> 4)) * PLANE;
            for (int j = t; j < PLANE/2; j += 256) {
                int r = j >> 5, wp = j & 31;
                unsigned v = *(const unsigned*)(sb + r*64 + wp*2);
                *(unsigned*)&sp[(r+8)*SW + wp*2 + 8] = v;
                __nv_bfloat162 bv = *(__nv_bfloat162*)&v;
                sp[SPN + (r+8)*SW + wp*2 + 7] = bv.x;  // odd copy shifted left 1
                sp[SPN + (r+8)*SW + wp*2 + 8] = bv.y;
            }
        }
        if (tb + 1 < NBANDS) CP_WAIT1(); else CP_WAIT0();
        __syncthreads();   // band tb data + satp visible to all

        // ---- compute band tb: 16 pipelined steps of 5 mmas ----
        int hb = (tb & 15) << 2;
        int bofft[5];
#pragma unroll
        for (int tt = 0; tt < 5; tt++) bofft[tt] = boff[tt] + hb * SW;
        unsigned abb = gshb + ((unsigned)(tb & 1) * BUFE + aoff) * 2u;

        unsigned A0[4], B0[10], A1[4], B1[10];
        // step s: hh = s>>2 (band row), w0 = (s&3)*16 (k chunk)
        {
            ldsm_x4(A0[0],A0[1],A0[2],A0[3], abb);
#pragma unroll
            for (int tt = 0; tt < 5; tt++) {
                const __nv_bfloat16* bp = sp + bofft[tt];
                B0[2*tt]   = *(const unsigned*)bp;
                B0[2*tt+1] = *(const unsigned*)(bp + 8);
            }
        }
#pragma unroll
        for (int u = 0; u < 8; u++) {
            {   // load step 2u+1
                int s = 2*u + 1;
                int hh = s >> 2, w0 = (s & 3) << 4;
                ldsm_x4(A1[0],A1[1],A1[2],A1[3], abb + (unsigned)((hh<<6)+w0)*2u);
                int off = hh * SW + w0;
#pragma unroll
                for (int tt = 0; tt < 5; tt++) {
                    const __nv_bfloat16* bp = sp + bofft[tt] + off;
                    B1[2*tt]   = *(const unsigned*)bp;
                    B1[2*tt+1] = *(const unsigned*)(bp + 8);
                }
            }
#pragma unroll
            for (int tt = 0; tt < 5; tt++)
                mma16816(acc[tt], A0[0],A0[1],A0[2],A0[3], B0[2*tt], B0[2*tt+1]);
            {   // load step (2u+2) & 15 (wraps to 0 on last pair: harmless reload)
                int s = (2*u + 2) & 15;
                int hh = s >> 2, w0 = (s & 3) << 4;
                ldsm_x4(A0[0],A0[1],A0[2],A0[3], abb + (unsigned)((hh<<6)+w0)*2u);
                int off = hh * SW + w0;
#pragma unroll
                for (int tt = 0; tt < 5; tt++) {
                    const __nv_bfloat16* bp = sp + bofft[tt] + off;
                    B0[2*tt]   = *(const unsigned*)bp;
                    B0[2*tt+1] = *(const unsigned*)(bp + 8);
                }
            }
#pragma unroll
            for (int tt = 0; tt < 5; tt++)
                mma16816(acc[tt], A1[0],A1[1],A1[2],A1[3], B1[2*tt], B1[2*tt+1]);
        }
    }

    // C layout: c0=C[grp][tig*2], c1=[grp][tig*2+1], c2=[grp+8][tig*2], c3=[grp+8][tig*2+1]
#pragma unroll
    for (int tt = 0; tt < 5; tt++) {
        int p0 = warp * 40 + tt * 8 + tig * 2;
        if (p0 < NPOS) {
            atomicAdd(&d_dot[(m * 16 + grp) * NPOS + p0],     acc[tt][0]);
            atomicAdd(&d_dot[(m * 16 + grp + 8) * NPOS + p0], acc[tt][2]);
            if (p0 + 1 < NPOS) {
                atomicAdd(&d_dot[(m * 16 + grp) * NPOS + p0 + 1],     acc[tt][1]);
                atomicAdd(&d_dot[(m * 16 + grp + 8) * NPOS + p0 + 1], acc[tt][3]);
            }
        }
    }
    (void)satf; (void)grdf;
}

// ---------------------------------------------------------------------------
__device__ __forceinline__ float softplusf(float x) {
    return fmaxf(x, 0.f) + log1pf(expf(-fabsf(x)));
}

// Finalize: sim -> dist -> loss terms. One block.
__global__ void k_final(float* __restrict__ out) {
    __shared__ float invp[NB * NPOS];
    __shared__ float gns[NB];
    __shared__ float dist[NB * NB];
    __shared__ float pos[NB];
    __shared__ float red[256];
    __shared__ float rowmin[NB];
    int t = threadIdx.x;

    for (int i = t; i < NB * NPOS; i += 256) invp[i] = rsqrtf(d_part[i]);
    if (t < NB) gns[t] = sqrtf(d_gsq[t]);
    __syncthreads();

    int m = t >> 4, n = t & 15;
    const float* dp = d_dot + t * NPOS;
    const float* ip = invp + m * NPOS;
    float best = -3.4e38f;
    for (int k = 0; k < NPOS; k++) best = fmaxf(best, dp[k] * ip[k]);
    float sim = best / gns[n];
    dist[t] = 2.f - 2.f * sim;
    __syncthreads();

    if (t < NB) pos[t] = dist[t * NB + t];
    __syncthreads();

    float x1 = (pos[n] - dist[t]) * 10.f;   // g2s: pos[None,:] - dist
    float x2 = (pos[m] - dist[t]) * 10.f;   // s2g: pos[:,None] - dist
    red[t] = softplusf(x1) + softplusf(x2);
    if (t < NB) {
        float mn = 3.4e38f;
        for (int k = 0; k < NB; k++) mn = fminf(mn, dist[t * NB + k]);
        rowmin[t] = mn;
    }
    __syncthreads();
    for (int s = 128; s > 0; s >>= 1) {
        if (t < s) red[t] += red[t + s];
        __syncthreads();
    }
    if (t == 0) {
        float pair_n = (float)(NB * (NB - 1));
        float loss = 10.f * (red[0] / (2.f * pair_n));
        float ps = 0.f, ms = 0.f;
        for (int k = 0; k < NB; k++) { ps += pos[k]; ms += rowmin[k]; }
        out[0] = loss;
        out[1] = ps / NB;
        out[2] = ms / NB;
    }
}

// ---------------------------------------------------------------------------
extern "C" void kernel_launch(void* const* d_in, const int* in_sizes, int n_in,
                              void* d_out, int out_size) {
    const float* sat = (const float*)d_in[0];
    const float* grd = (const float*)d_in[1];
    float* out = (float*)d_out;

    // k_corr_mma kept at launch index 3 so ncu's skip window captures it.
    k_zero<<<(NB * NB * NPOS + 255) / 256, 256>>>();
    k_prep_grd<<<dim3(NB, 8), 256>>>(grd);
    k_prep_sat<<<dim3(NB, 8), 256>>>(sat);
    k_corr_mma<<<dim3(NB, CSPL), 256>>>(sat, grd);
    k_part2<<<NB, 1024>>>();
    k_final<<<1, 256>>>(out);
}

// round 13
// speedup vs baseline: 8.6047x; 1.1049x over previous
#include <cuda_runtime.h>
#include <cuda_bf16.h>
#include <cstdint>
#include <math.h>

#define NB 16
#define NC 128
#define NH 64
#define NW 64
#define NS 17            // 2*8+1 shifts per axis
#define NPOS 289         // 17*17
#define PLANE (NH*NW)    // 4096
#define CHW (NC*PLANE)   // 524288

#define SW 82            // padded sat plane column stride
#define SROWS 84         // 64 + 16 shift + 2 spill rows (di<=18); SPN/2 mod 32 = 20 -> parity copies conflict-free
#define SPN (SROWS*SW)   // 6888 elements per copy
#define GSE 264          // grd smem n-stride elems (16B-aligned rows; 132 words mod 32 = 4 -> ldsm conflict-free)
#define BUFE (16*GSE)    // one grd band buffer (16 n x 256 k)
#define CSPL 32          // channel split (16 m x 32 splits = 512 blocks, ~3.5/SM single wave)
#define CPB (NC/CSPL)    // 4 channels per block
#define NBANDS (CPB*16)  // 64 4-row bands per block
#define NTILE 10         // p-tiles per warp (4 warps x 10 x 8 = 320)

// Persistent device scratch (no allocations allowed).
__device__ float d_dot[NB*NB*NPOS];            // raw correlation sums (atomic, zeroed in k_prep_grd)
__device__ float d_part[NB*NPOS];              // raw window energy sums
__device__ float d_gsqp[NB][8];                // ||grd_n||^2 partials (per channel split)
__device__ float d_energy[NB*PLANE];           // per-pixel channel-summed sat energy
__device__ __nv_bfloat16 d_satb[NB*CHW];       // bf16 copy of sat
__device__ __nv_bfloat16 d_grdb[NB*CHW];       // bf16 copy of grd

// ---------------------------------------------------------------------------
// grd: fp32 -> bf16 conversion fused with ||grd_n||^2 partial + d_dot zeroing.
__global__ void k_prep_grd(const float* __restrict__ grd) {
    int n = blockIdx.x, cs = blockIdx.y;   // 8 channel splits
    // fold d_dot zeroing in (this kernel completes before k_corr launches)
    int gid = (blockIdx.x * 8 + blockIdx.y) * blockDim.x + threadIdx.x;  // 0..32767
    for (int i = gid; i < NB*NB*NPOS; i += NB*8*256) d_dot[i] = 0.f;

    size_t base = (size_t)n * CHW + (size_t)cs * (CHW/8);
    const float4* src = (const float4*)(grd + base);
    uint2* dst = (uint2*)(d_grdb + base);
    float s = 0.f;
    for (int i = threadIdx.x; i < CHW/8/4; i += blockDim.x) {
        float4 v = src[i];
        s = fmaf(v.x, v.x, s); s = fmaf(v.y, v.y, s);
        s = fmaf(v.z, v.z, s); s = fmaf(v.w, v.w, s);
        __nv_bfloat162 lo = __floats2bfloat162_rn(v.x, v.y);
        __nv_bfloat162 hi = __floats2bfloat162_rn(v.z, v.w);
        uint2 o;
        o.x = *(unsigned*)&lo; o.y = *(unsigned*)&hi;
        dst[i] = o;
    }
    __shared__ float r[32];
    for (int o = 16; o > 0; o >>= 1) s += __shfl_down_sync(0xffffffffu, s, o);
    int lane = threadIdx.x & 31, wid = threadIdx.x >> 5;
    if (lane == 0) r[wid] = s;
    __syncthreads();
    if (wid == 0) {
        s = (lane < (int)(blockDim.x >> 5)) ? r[lane] : 0.f;
        for (int o = 16; o > 0; o >>= 1) s += __shfl_down_sync(0xffffffffu, s, o);
        if (lane == 0) d_gsqp[n][cs] = s;
    }
}

// ---------------------------------------------------------------------------
// sat: fp32 -> bf16 fused with per-pixel channel energy (no atomics):
// block = (m, 256-pixel chunk); thread owns one pixel, loops all 128 channels.
__global__ void k_prep_sat(const float* __restrict__ sat) {
    int m = blockIdx.x;
    int pix = blockIdx.y * 256 + threadIdx.x;
    const float* p = sat + (size_t)m * CHW + pix;
    __nv_bfloat16* q = d_satb + (size_t)m * CHW + pix;
    float s = 0.f;
#pragma unroll 4
    for (int c = 0; c < NC; c++) {
        float v = p[c * PLANE];
        s = fmaf(v, v, s);
        q[c * PLANE] = __float2bfloat16(v);
    }
    d_energy[m * PLANE + pix] = s;
}

// ---------------------------------------------------------------------------
// Separable window sums from d_energy.
__global__ void k_part2() {
    int m = blockIdx.x;
    __shared__ float e[PLANE];
    __shared__ float cw[NS * NH];
    for (int i = threadIdx.x; i < PLANE; i += blockDim.x)
        e[i] = d_energy[m * PLANE + i];
    __syncthreads();
    for (int t = threadIdx.x; t < NS * NH; t += blockDim.x) {
        int j = t / NH, h = t % NH;
        int lo = j - 8; if (lo < 0) lo = 0;
        int hi = j - 8 + 64; if (hi > NW) hi = NW;
        float s = 0.f;
        for (int w = lo; w < hi; w++) s += e[h * NW + w];
        cw[j * NH + h] = s;
    }
    __syncthreads();
    for (int t = threadIdx.x; t < NPOS; t += blockDim.x) {
        int i = t / NS, j = t % NS;
        int lo = i - 8; if (lo < 0) lo = 0;
        int hi = i - 8 + 64; if (hi > NH) hi = NH;
        float s = 0.f;
        for (int h = lo; h < hi; h++) s += cw[j * NH + h];
        d_part[m * NPOS + t] = s;
    }
}

// ---------------------------------------------------------------------------
__device__ __forceinline__ void mma16816(float* c,
    unsigned a0, unsigned a1, unsigned a2, unsigned a3,
    unsigned b0, unsigned b1) {
    asm volatile(
        "mma.sync.aligned.m16n8k16.row.col.f32.bf16.bf16.f32 "
        "{%0,%1,%2,%3}, {%4,%5,%6,%7}, {%8,%9}, {%0,%1,%2,%3};"
        : "+f"(c[0]), "+f"(c[1]), "+f"(c[2]), "+f"(c[3])
        : "r"(a0), "r"(a1), "r"(a2), "r"(a3), "r"(b0), "r"(b1));
}

__device__ __forceinline__ void ldsm_x4(unsigned& a0, unsigned& a1,
                                        unsigned& a2, unsigned& a3,
                                        unsigned saddr) {
    asm volatile("ldmatrix.sync.aligned.m8n8.x4.shared.b16 {%0,%1,%2,%3}, [%4];"
        : "=r"(a0), "=r"(a1), "=r"(a2), "=r"(a3) : "r"(saddr));
}

__device__ __forceinline__ void cpasync16(unsigned dst, const void* src) {
    asm volatile("cp.async.ca.shared.global [%0], [%1], 16;" :: "r"(dst), "l"(src));
}
#define CP_COMMIT() asm volatile("cp.async.commit_group;")
#define CP_WAIT1()  asm volatile("cp.async.wait_group 1;")
#define CP_WAIT0()  asm volatile("cp.async.wait_group 0;")

// ---------------------------------------------------------------------------
// Main correlation on tensor cores.
// Block = (m, channel-split of 4 channels). 128 threads = 4 warps.
// C[n=16, p=320] = sum_k grd[n,k]*satshift[k,p]. K tiled by 64 4-row bands.
// Warp w owns p in [w*80, w*80+80): 10 n8-tiles -> one ldsm.x4 A fetch
// feeds 10 mmas (A bytes halved vs 5-tile version; 307 B/mma total).
// grd bands double-buffered via cp.async; inner loop software-pipelined.
__global__ __launch_bounds__(128, 4)
void k_corr_mma(const float* __restrict__ satf, const float* __restrict__ grdf) {
    __shared__ __align__(16) __nv_bfloat16 sp[2 * SPN];   // dual-parity sat copies
    __shared__ __align__(16) __nv_bfloat16 gsh[2 * BUFE]; // double-buffered grd band

    int m = blockIdx.x;
    int c0 = blockIdx.y * CPB;
    int t = threadIdx.x;
    int lane = t & 31, warp = t >> 5;
    int tig = lane & 3, grp = lane >> 2;

    // Zero both sat copies once (borders + spill rows stay zero forever).
    for (int i = t; i < 2 * SPN; i += 128) sp[i] = __float2bfloat16(0.f);

    // Per-thread, per-tile B-fragment base offsets (constant over K loop).
    int boff[NTILE];
#pragma unroll
    for (int tt = 0; tt < NTILE; tt++) {
        int p = warp * 80 + tt * 8 + grp;        // B-frag column = groupID
        int di = p / 17, dj = p % 17;            // p<=319 -> di<=18 (zero spill rows)
        boff[tt] = (dj & 1) * SPN + di * SW + (dj & ~1) + tig * 2;
    }

    // ldmatrix A lane roles (validated R8 mapping).
    unsigned gshb = (unsigned)__cvta_generic_to_shared(gsh);
    int arow = (lane & 7) + ((lane >> 3) & 1) * 8;
    int akhi = (lane & 16) ? 8 : 0;
    unsigned aoff = (unsigned)(arow * GSE + akhi);

    float acc[NTILE][4];
#pragma unroll
    for (int tt = 0; tt < NTILE; tt++)
#pragma unroll
        for (int k = 0; k < 4; k++) acc[tt][k] = 0.f;

    // ---- cp.async copy of one grd band (16 n x 256 bf16) ----
    auto issue_copy = [&](int tb) {
        int buf = tb & 1;
        int c = c0 + (tb >> 4), bb = tb & 15;
#pragma unroll
        for (int i = 0; i < 4; i++) {
            int q = t + i * 128;
            int n = q >> 5, ch = q & 31;
            const __nv_bfloat16* src =
                d_grdb + ((size_t)(n * NC + c) * PLANE) + (bb << 8) + (ch << 3);
            unsigned dst = gshb + ((unsigned)buf*BUFE + (unsigned)(n*GSE) + (unsigned)(ch<<3)) * 2u;
            cpasync16(dst, src);
        }
    };

    // prologue: band 0 in flight
    issue_copy(0);
    CP_COMMIT();

    for (int tb = 0; tb < NBANDS; tb++) {
        __syncthreads();   // all warps done with previous band / satp reads
        if (tb + 1 < NBANDS) { issue_copy(tb + 1); CP_COMMIT(); }
        if ((tb & 15) == 0) {
            // load sat plane for channel tb>>4 (bf16 source), dual parity
            const __nv_bfloat16* sb = d_satb + (size_t)(m*NC + c0 + (tb >> 4)) * PLANE;
            for (int j = t; j < PLANE/2; j += 128) {
                int r = j >> 5, wp = j & 31;
                unsigned v = *(const unsigned*)(sb + r*64 + wp*2);
                *(unsigned*)&sp[(r+8)*SW + wp*2 + 8] = v;
                __nv_bfloat162 bv = *(__nv_bfloat162*)&v;
                sp[SPN + (r+8)*SW + wp*2 + 7] = bv.x;  // odd copy shifted left 1
                sp[SPN + (r+8)*SW + wp*2 + 8] = bv.y;
            }
        }
        if (tb + 1 < NBANDS) CP_WAIT1(); else CP_WAIT0();
        __syncthreads();   // band tb data + satp visible to all

        // ---- compute band tb: 16 pipelined steps of 10 mmas ----
        int hb = (tb & 15) << 2;
        int bofft[NTILE];
#pragma unroll
        for (int tt = 0; tt < NTILE; tt++) bofft[tt] = boff[tt] + hb * SW;
        unsigned abb = gshb + ((unsigned)(tb & 1) * BUFE + aoff) * 2u;

        unsigned A0[4], B0[2*NTILE], A1[4], B1[2*NTILE];
        // step s: hh = s>>2 (band row), w0 = (s&3)*16 (k chunk)
        {
            ldsm_x4(A0[0],A0[1],A0[2],A0[3], abb);
#pragma unroll
            for (int tt = 0; tt < NTILE; tt++) {
                const __nv_bfloat16* bp = sp + bofft[tt];
                B0[2*tt]   = *(const unsigned*)bp;
                B0[2*tt+1] = *(const unsigned*)(bp + 8);
            }
        }
#pragma unroll
        for (int u = 0; u < 8; u++) {
            {   // load step 2u+1
                int s = 2*u + 1;
                int hh = s >> 2, w0 = (s & 3) << 4;
                ldsm_x4(A1[0],A1[1],A1[2],A1[3], abb + (unsigned)((hh<<6)+w0)*2u);
                int off = hh * SW + w0;
#pragma unroll
                for (int tt = 0; tt < NTILE; tt++) {
                    const __nv_bfloat16* bp = sp + bofft[tt] + off;
                    B1[2*tt]   = *(const unsigned*)bp;
                    B1[2*tt+1] = *(const unsigned*)(bp + 8);
                }
            }
#pragma unroll
            for (int tt = 0; tt < NTILE; tt++)
                mma16816(acc[tt], A0[0],A0[1],A0[2],A0[3], B0[2*tt], B0[2*tt+1]);
            {   // load step (2u+2) & 15 (wraps to 0 on last pair: harmless reload)
                int s = (2*u + 2) & 15;
                int hh = s >> 2, w0 = (s & 3) << 4;
                ldsm_x4(A0[0],A0[1],A0[2],A0[3], abb + (unsigned)((hh<<6)+w0)*2u);
                int off = hh * SW + w0;
#pragma unroll
                for (int tt = 0; tt < NTILE; tt++) {
                    const __nv_bfloat16* bp = sp + bofft[tt] + off;
                    B0[2*tt]   = *(const unsigned*)bp;
                    B0[2*tt+1] = *(const unsigned*)(bp + 8);
                }
            }
#pragma unroll
            for (int tt = 0; tt < NTILE; tt++)
                mma16816(acc[tt], A1[0],A1[1],A1[2],A1[3], B1[2*tt], B1[2*tt+1]);
        }
    }

    // C layout: c0=C[grp][tig*2], c1=[grp][tig*2+1], c2=[grp+8][tig*2], c3=[grp+8][tig*2+1]
#pragma unroll
    for (int tt = 0; tt < NTILE; tt++) {
        int p0 = warp * 80 + tt * 8 + tig * 2;
        if (p0 < NPOS) {
            atomicAdd(&d_dot[(m * 16 + grp) * NPOS + p0],     acc[tt][0]);
            atomicAdd(&d_dot[(m * 16 + grp + 8) * NPOS + p0], acc[tt][2]);
            if (p0 + 1 < NPOS) {
                atomicAdd(&d_dot[(m * 16 + grp) * NPOS + p0 + 1],     acc[tt][1]);
                atomicAdd(&d_dot[(m * 16 + grp + 8) * NPOS + p0 + 1], acc[tt][3]);
            }
        }
    }
    (void)satf; (void)grdf;
}

// ---------------------------------------------------------------------------
__device__ __forceinline__ float softplusf(float x) {
    return fmaxf(x, 0.f) + log1pf(expf(-fabsf(x)));
}

// Finalize: sim -> dist -> loss terms. One block of 1024 (4 threads per pair).
__global__ void k_final(float* __restrict__ out) {
    __shared__ float invp[NB * NPOS];
    __shared__ float gns[NB];
    __shared__ float dist[NB * NB];
    __shared__ float pos[NB];
    __shared__ float red[256];
    __shared__ float rowmin[NB];
    int t = threadIdx.x;

    for (int i = t; i < NB * NPOS; i += 1024) invp[i] = rsqrtf(d_part[i]);
    if (t < NB) {
        float s = 0.f;
        for (int j = 0; j < 8; j++) s += d_gsqp[t][j];
        gns[t] = sqrtf(s);
    }
    __syncthreads();

    int pair = t >> 2, sub = t & 3;
    int m = pair >> 4, n = pair & 15;
    const float* dp = d_dot + pair * NPOS;
    const float* ip = invp + m * NPOS;
    float best = -3.4e38f;
    for (int k = sub; k < NPOS; k += 4) best = fmaxf(best, dp[k] * ip[k]);
    best = fmaxf(best, __shfl_xor_sync(0xffffffffu, best, 1));
    best = fmaxf(best, __shfl_xor_sync(0xffffffffu, best, 2));
    if (sub == 0) {
        float sim = best / gns[n];
        dist[pair] = 2.f - 2.f * sim;
    }
    __syncthreads();

    if (t < NB) pos[t] = dist[t * NB + t];
    __syncthreads();

    if (t < 256) {
        int mm = t >> 4, nn = t & 15;
        float x1 = (pos[nn] - dist[t]) * 10.f;   // g2s: pos[None,:] - dist
        float x2 = (pos[mm] - dist[t]) * 10.f;   // s2g: pos[:,None] - dist
        red[t] = softplusf(x1) + softplusf(x2);
    }
    if (t < NB) {
        float mn = 3.4e38f;
        for (int k = 0; k < NB; k++) mn = fminf(mn, dist[t * NB + k]);
        rowmin[t] = mn;
    }
    __syncthreads();
    for (int s = 128; s > 0; s >>= 1) {
        if (t < s) red[t] += red[t + s];
        __syncthreads();
    }
    if (t == 0) {
        float pair_n = (float)(NB * (NB - 1));
        float loss = 10.f * (red[0] / (2.f * pair_n));
        float ps = 0.f, ms = 0.f;
        for (int k = 0; k < NB; k++) { ps += pos[k]; ms += rowmin[k]; }
        out[0] = loss;
        out[1] = ps / NB;
        out[2] = ms / NB;
    }
}

// ---------------------------------------------------------------------------
extern "C" void kernel_launch(void* const* d_in, const int* in_sizes, int n_in,
                              void* d_out, int out_size) {
    const float* sat = (const float*)d_in[0];
    const float* grd = (const float*)d_in[1];
    float* out = (float*)d_out;

    k_prep_grd<<<dim3(NB, 8), 256>>>(grd);   // also zeroes d_dot
    k_prep_sat<<<dim3(NB, 16), 256>>>(sat);
    k_part2<<<NB, 1024>>>();
    k_corr_mma<<<dim3(NB, CSPL), 128>>>(sat, grd);
    k_final<<<1, 1024>>>(out);
}

// round 15
// speedup vs baseline: 9.4815x; 1.1019x over previous
#include <cuda_runtime.h>
#include <cuda_bf16.h>
#include <cstdint>
#include <math.h>

#define NB 16
#define NC 128
#define NH 64
#define NW 64
#define NS 17            // 2*8+1 shifts per axis
#define NPOS 289         // 17*17
#define PLANE (NH*NW)    // 4096
#define CHW (NC*PLANE)   // 524288

#define SW 82            // padded sat plane column stride
#define SROWS 84         // 64 + 16 shift + 2 spill rows (di<=18); SPN/2 mod 32 = 20 -> parity copies conflict-free
#define SPN (SROWS*SW)   // 6888 elements per copy
#define GSE 264          // grd smem n-stride elems (16B-aligned rows; 132 words mod 32 = 4 -> ldsm conflict-free)
#define BUFE (16*GSE)    // one grd band buffer (16 n x 256 k)
#define CSPL 37          // k-split: 16 m x 37 = 592 blocks = exactly 4/SM on 148 SMs
#define NBT (NC*16)      // 2048 total 4-row bands per m
#define NTILE 10         // p-tiles per warp (4 warps x 10 x 8 = 320)

// Persistent device scratch (no allocations allowed).
__device__ float d_dot[NB*NB*NPOS];            // raw correlation sums (atomic, zeroed in k_prep)
__device__ float d_part[NB*NPOS];              // raw window energy sums
__device__ float d_gsqp[NB][8];                // ||grd_n||^2 partials (per channel split)
__device__ __nv_bfloat16 d_satb[NB*CHW];       // bf16 copy of sat
__device__ __nv_bfloat16 d_grdb[NB*CHW];       // bf16 copy of grd

// ---------------------------------------------------------------------------
// Fused prologue. grid (NB, 9), 1024 threads.
//  y == 0 : sat block m=x: fp32->bf16 convert + per-pixel channel energy
//           (thread owns 4 consecutive pixels, loops channels; fully
//           coalesced) + separable window sums -> d_part[m]. Replaces
//           k_prep_sat + k_part2.
//  y >= 1 : grd chunk (n=x, cs=y-1): fp32->bf16 convert + gsq partial +
//           distributed d_dot zeroing.
__global__ __launch_bounds__(1024)
void k_prep(const float* __restrict__ satf, const float* __restrict__ grdf) {
    int t = threadIdx.x;
    if (blockIdx.y == 0) {
        int m = blockIdx.x;
        __shared__ float e[PLANE];
        __shared__ float cw[NS * NH];
        const float4* src = (const float4*)(satf + (size_t)m * CHW);
        uint2* dst = (uint2*)(d_satb + (size_t)m * CHW);
        float a0 = 0.f, a1 = 0.f, a2 = 0.f, a3 = 0.f;
        // float4 index t + c*1024 covers pixels 4t..4t+3 of channel c.
#pragma unroll 4
        for (int c = 0; c < NC; c++) {
            float4 v = src[t + c * 1024];
            a0 = fmaf(v.x, v.x, a0); a1 = fmaf(v.y, v.y, a1);
            a2 = fmaf(v.z, v.z, a2); a3 = fmaf(v.w, v.w, a3);
            __nv_bfloat162 lo = __floats2bfloat162_rn(v.x, v.y);
            __nv_bfloat162 hi = __floats2bfloat162_rn(v.z, v.w);
            uint2 o; o.x = *(unsigned*)&lo; o.y = *(unsigned*)&hi;
            dst[t + c * 1024] = o;
        }
        e[4*t+0] = a0; e[4*t+1] = a1; e[4*t+2] = a2; e[4*t+3] = a3;
        __syncthreads();
        for (int k = t; k < NS * NH; k += 1024) {
            int j = k / NH, h = k % NH;
            int lo = j - 8; if (lo < 0) lo = 0;
            int hi = j - 8 + 64; if (hi > NW) hi = NW;
            float s = 0.f;
            for (int w = lo; w < hi; w++) s += e[h * NW + w];
            cw[j * NH + h] = s;
        }
        __syncthreads();
        for (int k = t; k < NPOS; k += 1024) {
            int i = k / NS, j = k % NS;
            int lo = i - 8; if (lo < 0) lo = 0;
            int hi = i - 8 + 64; if (hi > NH) hi = NH;
            float s = 0.f;
            for (int h = lo; h < hi; h++) s += cw[j * NH + h];
            d_part[m * NPOS + k] = s;
        }
    } else {
        int n = blockIdx.x, cs = blockIdx.y - 1;   // cs in [0,8)
        int gid = (n * 8 + cs) * 1024 + t;         // 131072 threads >= 73984
        if (gid < NB * NB * NPOS) d_dot[gid] = 0.f;

        size_t base = (size_t)n * CHW + (size_t)cs * (CHW / 8);
        const float4* src = (const float4*)(grdf + base);
        uint2* dst = (uint2*)(d_grdb + base);
        float s = 0.f;
#pragma unroll 4
        for (int i = t; i < CHW / 8 / 4; i += 1024) {
            float4 v = src[i];
            s = fmaf(v.x, v.x, s); s = fmaf(v.y, v.y, s);
            s = fmaf(v.z, v.z, s); s = fmaf(v.w, v.w, s);
            __nv_bfloat162 lo = __floats2bfloat162_rn(v.x, v.y);
            __nv_bfloat162 hi = __floats2bfloat162_rn(v.z, v.w);
            uint2 o; o.x = *(unsigned*)&lo; o.y = *(unsigned*)&hi;
            dst[i] = o;
        }
        __shared__ float r[32];
        for (int o = 16; o > 0; o >>= 1) s += __shfl_down_sync(0xffffffffu, s, o);
        int lane = t & 31, wid = t >> 5;
        if (lane == 0) r[wid] = s;
        __syncthreads();
        if (wid == 0) {
            s = (lane < 32) ? r[lane] : 0.f;
            for (int o = 16; o > 0; o >>= 1) s += __shfl_down_sync(0xffffffffu, s, o);
            if (lane == 0) d_gsqp[n][cs] = s;
        }
    }
}

// ---------------------------------------------------------------------------
__device__ __forceinline__ void mma16816(float* c,
    unsigned a0, unsigned a1, unsigned a2, unsigned a3,
    unsigned b0, unsigned b1) {
    asm volatile(
        "mma.sync.aligned.m16n8k16.row.col.f32.bf16.bf16.f32 "
        "{%0,%1,%2,%3}, {%4,%5,%6,%7}, {%8,%9}, {%0,%1,%2,%3};"
        : "+f"(c[0]), "+f"(c[1]), "+f"(c[2]), "+f"(c[3])
        : "r"(a0), "r"(a1), "r"(a2), "r"(a3), "r"(b0), "r"(b1));
}

__device__ __forceinline__ void ldsm_x4(unsigned& a0, unsigned& a1,
                                        unsigned& a2, unsigned& a3,
                                        unsigned saddr) {
    asm volatile("ldmatrix.sync.aligned.m8n8.x4.shared.b16 {%0,%1,%2,%3}, [%4];"
        : "=r"(a0), "=r"(a1), "=r"(a2), "=r"(a3) : "r"(saddr));
}

__device__ __forceinline__ void cpasync16(unsigned dst, const void* src) {
    asm volatile("cp.async.ca.shared.global [%0], [%1], 16;" :: "r"(dst), "l"(src));
}
#define CP_COMMIT() asm volatile("cp.async.commit_group;")
#define CP_WAIT1()  asm volatile("cp.async.wait_group 1;")
#define CP_WAIT0()  asm volatile("cp.async.wait_group 0;")

// ---------------------------------------------------------------------------
// Main correlation on tensor cores.
// Block = (m, k-split by of [tbeg,tend) 4-row bands); 592 blocks = 4/SM.
// 128 threads = 4 warps. C[n=16, p=320] = sum_k grd[n,k]*satshift[k,p].
// Warp w owns p in [w*80, w*80+80): 10 n8-tiles; one ldsm.x4 A fetch
// feeds 10 mmas. grd bands double-buffered via cp.async; software-pipelined.
__global__ __launch_bounds__(128, 4)
void k_corr_mma(const float* __restrict__ satf, const float* __restrict__ grdf) {
    __shared__ __align__(16) __nv_bfloat16 sp[2 * SPN];   // dual-parity sat copies
    __shared__ __align__(16) __nv_bfloat16 gsh[2 * BUFE]; // double-buffered grd band

    int m = blockIdx.x;
    int tbeg = (blockIdx.y * NBT) / CSPL;
    int tend = ((blockIdx.y + 1) * NBT) / CSPL;
    int t = threadIdx.x;
    int lane = t & 31, warp = t >> 5;
    int tig = lane & 3, grp = lane >> 2;

    // Zero both sat copies once (borders + spill rows stay zero forever).
    for (int i = t; i < 2 * SPN; i += 128) sp[i] = __float2bfloat16(0.f);

    // Per-thread, per-tile B-fragment base offsets (constant over K loop).
    int boff[NTILE];
#pragma unroll
    for (int tt = 0; tt < NTILE; tt++) {
        int p = warp * 80 + tt * 8 + grp;        // B-frag column = groupID
        int di = p / 17, dj = p % 17;            // p<=319 -> di<=18 (zero spill rows)
        boff[tt] = (dj & 1) * SPN + di * SW + (dj & ~1) + tig * 2;
    }

    // ldmatrix A lane roles (validated R8 mapping).
    unsigned gshb = (unsigned)__cvta_generic_to_shared(gsh);
    int arow = (lane & 7) + ((lane >> 3) & 1) * 8;
    int akhi = (lane & 16) ? 8 : 0;
    unsigned aoff = (unsigned)(arow * GSE + akhi);

    float acc[NTILE][4];
#pragma unroll
    for (int tt = 0; tt < NTILE; tt++)
#pragma unroll
        for (int k = 0; k < 4; k++) acc[tt][k] = 0.f;

    // ---- cp.async copy of one grd band (16 n x 256 bf16) ----
    auto issue_copy = [&](int tb) {
        int buf = tb & 1;
        int c = tb >> 4, bb = tb & 15;
#pragma unroll
        for (int i = 0; i < 4; i++) {
            int q = t + i * 128;
            int n = q >> 5, ch = q & 31;
            const __nv_bfloat16* src =
                d_grdb + ((size_t)(n * NC + c) * PLANE) + (bb << 8) + (ch << 3);
            unsigned dst = gshb + ((unsigned)buf*BUFE + (unsigned)(n*GSE) + (unsigned)(ch<<3)) * 2u;
            cpasync16(dst, src);
        }
    };

    // prologue: first band in flight
    issue_copy(tbeg);
    CP_COMMIT();

    for (int tb = tbeg; tb < tend; tb++) {
        __syncthreads();   // all warps done with previous band / satp reads
        if (tb + 1 < tend) { issue_copy(tb + 1); CP_COMMIT(); }
        if (tb == tbeg || (tb & 15) == 0) {
            // load sat plane for channel tb>>4 (bf16 source), dual parity
            const __nv_bfloat16* sb = d_satb + (size_t)(m*NC + (tb >> 4)) * PLANE;
            for (int j = t; j < PLANE/2; j += 128) {
                int r = j >> 5, wp = j & 31;
                unsigned v = *(const unsigned*)(sb + r*64 + wp*2);
                *(unsigned*)&sp[(r+8)*SW + wp*2 + 8] = v;
                __nv_bfloat162 bv = *(__nv_bfloat162*)&v;
                sp[SPN + (r+8)*SW + wp*2 + 7] = bv.x;  // odd copy shifted left 1
                sp[SPN + (r+8)*SW + wp*2 + 8] = bv.y;
            }
        }
        if (tb + 1 < tend) CP_WAIT1(); else CP_WAIT0();
        __syncthreads();   // band tb data + satp visible to all

        // ---- compute band tb: 16 pipelined steps of 10 mmas ----
        int hb = (tb & 15) << 2;
        int bofft[NTILE];
#pragma unroll
        for (int tt = 0; tt < NTILE; tt++) bofft[tt] = boff[tt] + hb * SW;
        unsigned abb = gshb + ((unsigned)(tb & 1) * BUFE + aoff) * 2u;

        unsigned A0[4], B0[2*NTILE], A1[4], B1[2*NTILE];
        // step s: hh = s>>2 (band row), w0 = (s&3)*16 (k chunk)
        {
            ldsm_x4(A0[0],A0[1],A0[2],A0[3], abb);
#pragma unroll
            for (int tt = 0; tt < NTILE; tt++) {
                const __nv_bfloat16* bp = sp + bofft[tt];
                B0[2*tt]   = *(const unsigned*)bp;
                B0[2*tt+1] = *(const unsigned*)(bp + 8);
            }
        }
#pragma unroll
        for (int u = 0; u < 8; u++) {
            {   // load step 2u+1
                int s = 2*u + 1;
                int hh = s >> 2, w0 = (s & 3) << 4;
                ldsm_x4(A1[0],A1[1],A1[2],A1[3], abb + (unsigned)((hh<<6)+w0)*2u);
                int off = hh * SW + w0;
#pragma unroll
                for (int tt = 0; tt < NTILE; tt++) {
                    const __nv_bfloat16* bp = sp + bofft[tt] + off;
                    B1[2*tt]   = *(const unsigned*)bp;
                    B1[2*tt+1] = *(const unsigned*)(bp + 8);
                }
            }
#pragma unroll
            for (int tt = 0; tt < NTILE; tt++)
                mma16816(acc[tt], A0[0],A0[1],A0[2],A0[3], B0[2*tt], B0[2*tt+1]);
            {   // load step (2u+2) & 15 (wraps to 0 on last pair: harmless reload)
                int s = (2*u + 2) & 15;
                int hh = s >> 2, w0 = (s & 3) << 4;
                ldsm_x4(A0[0],A0[1],A0[2],A0[3], abb + (unsigned)((hh<<6)+w0)*2u);
                int off = hh * SW + w0;
#pragma unroll
                for (int tt = 0; tt < NTILE; tt++) {
                    const __nv_bfloat16* bp = sp + bofft[tt] + off;
                    B0[2*tt]   = *(const unsigned*)bp;
                    B0[2*tt+1] = *(const unsigned*)(bp + 8);
                }
            }
#pragma unroll
            for (int tt = 0; tt < NTILE; tt++)
                mma16816(acc[tt], A1[0],A1[1],A1[2],A1[3], B1[2*tt], B1[2*tt+1]);
        }
    }

    // C layout: c0=C[grp][tig*2], c1=[grp][tig*2+1], c2=[grp+8][tig*2], c3=[grp+8][tig*2+1]
#pragma unroll
    for (int tt = 0; tt < NTILE; tt++) {
        int p0 = warp * 80 + tt * 8 + tig * 2;
        if (p0 < NPOS) {
            atomicAdd(&d_dot[(m * 16 + grp) * NPOS + p0],     acc[tt][0]);
            atomicAdd(&d_dot[(m * 16 + grp + 8) * NPOS + p0], acc[tt][2]);
            if (p0 + 1 < NPOS) {
                atomicAdd(&d_dot[(m * 16 + grp) * NPOS + p0 + 1],     acc[tt][1]);
                atomicAdd(&d_dot[(m * 16 + grp + 8) * NPOS + p0 + 1], acc[tt][3]);
            }
        }
    }
    (void)satf; (void)grdf;
}

// ---------------------------------------------------------------------------
__device__ __forceinline__ float softplusf(float x) {
    return fmaxf(x, 0.f) + log1pf(expf(-fabsf(x)));
}

// Finalize: sim -> dist -> loss terms. One block of 1024 (4 threads per pair).
__global__ void k_final(float* __restrict__ out) {
    __shared__ float invp[NB * NPOS];
    __shared__ float gns[NB];
    __shared__ float dist[NB * NB];
    __shared__ float pos[NB];
    __shared__ float red[256];
    __shared__ float rowmin[NB];
    int t = threadIdx.x;

    for (int i = t; i < NB * NPOS; i += 1024) invp[i] = rsqrtf(d_part[i]);
    if (t < NB) {
        float s = 0.f;
        for (int j = 0; j < 8; j++) s += d_gsqp[t][j];
        gns[t] = sqrtf(s);
    }
    __syncthreads();

    int pair = t >> 2, sub = t & 3;
    int m = pair >> 4, n = pair & 15;
    const float* dp = d_dot + pair * NPOS;
    const float* ip = invp + m * NPOS;
    float best = -3.4e38f;
    for (int k = sub; k < NPOS; k += 4) best = fmaxf(best, dp[k] * ip[k]);
    best = fmaxf(best, __shfl_xor_sync(0xffffffffu, best, 1));
    best = fmaxf(best, __shfl_xor_sync(0xffffffffu, best, 2));
    if (sub == 0) {
        float sim = best / gns[n];
        dist[pair] = 2.f - 2.f * sim;
    }
    __syncthreads();

    if (t < NB) pos[t] = dist[t * NB + t];
    __syncthreads();

    if (t < 256) {
        int mm = t >> 4, nn = t & 15;
        float x1 = (pos[nn] - dist[t]) * 10.f;   // g2s: pos[None,:] - dist
        float x2 = (pos[mm] - dist[t]) * 10.f;   // s2g: pos[:,None] - dist
        red[t] = softplusf(x1) + softplusf(x2);
    }
    if (t < NB) {
        float mn = 3.4e38f;
        for (int k = 0; k < NB; k++) mn = fminf(mn, dist[t * NB + k]);
        rowmin[t] = mn;
    }
    __syncthreads();
    for (int s = 128; s > 0; s >>= 1) {
        if (t < s) red[t] += red[t + s];
        __syncthreads();
    }
    if (t == 0) {
        float pair_n = (float)(NB * (NB - 1));
        float loss = 10.f * (red[0] / (2.f * pair_n));
        float ps = 0.f, ms = 0.f;
        for (int k = 0; k < NB; k++) { ps += pos[k]; ms += rowmin[k]; }
        out[0] = loss;
        out[1] = ps / NB;
        out[2] = ms / NB;
    }
}

// ---------------------------------------------------------------------------
extern "C" void kernel_launch(void* const* d_in, const int* in_sizes, int n_in,
                              void* d_out, int out_size) {
    const float* sat = (const float*)d_in[0];
    const float* grd = (const float*)d_in[1];
    float* out = (float*)d_out;

    k_prep<<<dim3(NB, 9), 1024>>>(sat, grd);   // convert+energy+part+gsq+zero
    k_corr_mma<<<dim3(NB, CSPL), 128>>>(sat, grd);
    k_final<<<1, 1024>>>(out);
}

// round 16
// speedup vs baseline: 10.1205x; 1.0674x over previous
#include <cuda_runtime.h>
#include <cuda_bf16.h>
#include <cstdint>
#include <math.h>

#define NB 16
#define NC 128
#define NH 64
#define NW 64
#define NS 17            // 2*8+1 shifts per axis
#define NPOS 289         // 17*17
#define PLANE (NH*NW)    // 4096
#define CHW (NC*PLANE)   // 524288

#define SW 82            // padded sat plane column stride
#define SROWS 84         // 64 + 16 shift + 2 spill rows (di<=18); SPN/2 mod 32 = 20 -> parity copies conflict-free
#define SPN (SROWS*SW)   // 6888 elements per copy
#define GSE 264          // grd smem n-stride elems (16B-aligned rows; 132 words mod 32 = 4 -> ldsm conflict-free)
#define BUFE (16*GSE)    // one grd band buffer (16 n x 256 k)
#define NSTAGE 3         // cp.async ring depth
#define CSPL 37          // k-split: 16 m x 37 = 592 blocks = exactly 4/SM on 148 SMs
#define NBT (NC*16)      // 2048 total 4-row bands per m
#define NTILE 10         // p-tiles per warp (4 warps x 10 x 8 = 320)

#define SMEM_CORR (2*SPN*2 + NSTAGE*BUFE*2)   // 27552 + 25344 = 52896 B

// Persistent device scratch (no allocations allowed).
__device__ float d_dot[NB*NB*NPOS];            // raw correlation sums (atomic, zeroed in k_prep)
__device__ float d_part[NB*NPOS];              // raw window energy sums
__device__ float d_gsqp[NB][8];                // ||grd_n||^2 partials (per channel split)
__device__ float d_epart[NB*16*PLANE];         // per-(m, 8-ch group) energy partials
__device__ __nv_bfloat16 d_satb[NB*CHW];       // bf16 copy of sat
__device__ __nv_bfloat16 d_grdb[NB*CHW];       // bf16 copy of grd

// ---------------------------------------------------------------------------
// Fused prologue. grid (NB, 24), 1024 threads. 384 balanced blocks.
//  y in [0,16) : sat (m=x, cgroup=y of 8 channels): fp32->bf16 convert +
//                per-pixel 8-channel energy partial -> d_epart (no atomics).
//  y in [16,24): grd (n=x, cs=y-16 of 16 channels): fp32->bf16 convert +
//                gsq partial + distributed d_dot zeroing.
__global__ __launch_bounds__(1024)
void k_prep(const float* __restrict__ satf, const float* __restrict__ grdf) {
    int t = threadIdx.x;
    if (blockIdx.y < 16) {
        int m = blockIdx.x, cg = blockIdx.y;
        const float4* src = (const float4*)(satf + (size_t)m * CHW) + cg * 8 * 1024;
        uint2* dst = (uint2*)(d_satb + (size_t)m * CHW) + cg * 8 * 1024;
        float a0 = 0.f, a1 = 0.f, a2 = 0.f, a3 = 0.f;
#pragma unroll
        for (int c = 0; c < 8; c++) {
            float4 v = src[t + c * 1024];
            a0 = fmaf(v.x, v.x, a0); a1 = fmaf(v.y, v.y, a1);
            a2 = fmaf(v.z, v.z, a2); a3 = fmaf(v.w, v.w, a3);
            __nv_bfloat162 lo = __floats2bfloat162_rn(v.x, v.y);
            __nv_bfloat162 hi = __floats2bfloat162_rn(v.z, v.w);
            uint2 o; o.x = *(unsigned*)&lo; o.y = *(unsigned*)&hi;
            dst[t + c * 1024] = o;
        }
        float4 e; e.x = a0; e.y = a1; e.z = a2; e.w = a3;
        ((float4*)d_epart)[(m * 16 + cg) * 1024 + t] = e;
    } else {
        int n = blockIdx.x, cs = blockIdx.y - 16;  // cs in [0,8)
        int gid = (n * 8 + cs) * 1024 + t;         // 131072 threads >= 73984
        if (gid < NB * NB * NPOS) d_dot[gid] = 0.f;

        size_t base = (size_t)n * CHW + (size_t)cs * (CHW / 8);
        const float4* src = (const float4*)(grdf + base);
        uint2* dst = (uint2*)(d_grdb + base);
        float s = 0.f;
#pragma unroll 4
        for (int i = t; i < CHW / 8 / 4; i += 1024) {
            float4 v = src[i];
            s = fmaf(v.x, v.x, s); s = fmaf(v.y, v.y, s);
            s = fmaf(v.z, v.z, s); s = fmaf(v.w, v.w, s);
            __nv_bfloat162 lo = __floats2bfloat162_rn(v.x, v.y);
            __nv_bfloat162 hi = __floats2bfloat162_rn(v.z, v.w);
            uint2 o; o.x = *(unsigned*)&lo; o.y = *(unsigned*)&hi;
            dst[i] = o;
        }
        __shared__ float r[32];
        for (int o = 16; o > 0; o >>= 1) s += __shfl_down_sync(0xffffffffu, s, o);
        int lane = t & 31, wid = t >> 5;
        if (lane == 0) r[wid] = s;
        __syncthreads();
        if (wid == 0) {
            s = (lane < 32) ? r[lane] : 0.f;
            for (int o = 16; o > 0; o >>= 1) s += __shfl_down_sync(0xffffffffu, s, o);
            if (lane == 0) d_gsqp[n][cs] = s;
        }
    }
}

// ---------------------------------------------------------------------------
// Window sums: sum 16 energy partials, then separable window sums -> d_part.
__global__ __launch_bounds__(1024)
void k_part2() {
    int m = blockIdx.x;
    int t = threadIdx.x;
    __shared__ float e[PLANE];
    __shared__ float cw[NS * NH];
    float4 s; s.x = s.y = s.z = s.w = 0.f;
#pragma unroll
    for (int cg = 0; cg < 16; cg++) {
        float4 v = ((const float4*)d_epart)[(m * 16 + cg) * 1024 + t];
        s.x += v.x; s.y += v.y; s.z += v.z; s.w += v.w;
    }
    ((float4*)e)[t] = s;
    __syncthreads();
    for (int k = t; k < NS * NH; k += 1024) {
        int j = k / NH, h = k % NH;
        int lo = j - 8; if (lo < 0) lo = 0;
        int hi = j - 8 + 64; if (hi > NW) hi = NW;
        float v = 0.f;
        for (int w = lo; w < hi; w++) v += e[h * NW + w];
        cw[j * NH + h] = v;
    }
    __syncthreads();
    for (int k = t; k < NPOS; k += 1024) {
        int i = k / NS, j = k % NS;
        int lo = i - 8; if (lo < 0) lo = 0;
        int hi = i - 8 + 64; if (hi > NH) hi = NH;
        float v = 0.f;
        for (int h = lo; h < hi; h++) v += cw[j * NH + h];
        d_part[m * NPOS + k] = v;
    }
}

// ---------------------------------------------------------------------------
__device__ __forceinline__ void mma16816(float* c,
    unsigned a0, unsigned a1, unsigned a2, unsigned a3,
    unsigned b0, unsigned b1) {
    asm volatile(
        "mma.sync.aligned.m16n8k16.row.col.f32.bf16.bf16.f32 "
        "{%0,%1,%2,%3}, {%4,%5,%6,%7}, {%8,%9}, {%0,%1,%2,%3};"
        : "+f"(c[0]), "+f"(c[1]), "+f"(c[2]), "+f"(c[3])
        : "r"(a0), "r"(a1), "r"(a2), "r"(a3), "r"(b0), "r"(b1));
}

__device__ __forceinline__ void ldsm_x4(unsigned& a0, unsigned& a1,
                                        unsigned& a2, unsigned& a3,
                                        unsigned saddr) {
    asm volatile("ldmatrix.sync.aligned.m8n8.x4.shared.b16 {%0,%1,%2,%3}, [%4];"
        : "=r"(a0), "=r"(a1), "=r"(a2), "=r"(a3) : "r"(saddr));
}

__device__ __forceinline__ void cpasync16(unsigned dst, const void* src) {
    asm volatile("cp.async.ca.shared.global [%0], [%1], 16;" :: "r"(dst), "l"(src));
}
#define CP_COMMIT() asm volatile("cp.async.commit_group;")
#define CP_WAIT2()  asm volatile("cp.async.wait_group 2;")
#define CP_WAIT1()  asm volatile("cp.async.wait_group 1;")
#define CP_WAIT0()  asm volatile("cp.async.wait_group 0;")

// ---------------------------------------------------------------------------
// Main correlation on tensor cores.
// Block = (m, k-split of [tbeg,tend) 4-row bands); 592 blocks = 4/SM.
// 128 threads = 4 warps. C[n=16, p=320] = sum_k grd[n,k]*satshift[k,p].
// Warp w owns p in [w*80, w*80+80): 10 n8-tiles; one ldsm.x4 A fetch feeds
// 10 mmas. grd bands in a 3-stage cp.async ring (2-band prefetch lead);
// inner loop software-pipelined. Dynamic smem (52.9 KB > 48 KB static cap).
__global__ __launch_bounds__(128, 4)
void k_corr_mma(const float* __restrict__ satf, const float* __restrict__ grdf) {
    extern __shared__ __align__(16) char smem_raw[];
    __nv_bfloat16* sp  = (__nv_bfloat16*)smem_raw;               // 2*SPN dual-parity sat
    __nv_bfloat16* gsh = (__nv_bfloat16*)(smem_raw + 2*SPN*2);   // NSTAGE*BUFE grd ring

    int m = blockIdx.x;
    int tbeg = (blockIdx.y * NBT) / CSPL;
    int tend = ((blockIdx.y + 1) * NBT) / CSPL;
    int t = threadIdx.x;
    int lane = t & 31, warp = t >> 5;
    int tig = lane & 3, grp = lane >> 2;

    // Zero both sat copies once (borders + spill rows stay zero forever).
    for (int i = t; i < 2 * SPN; i += 128) sp[i] = __float2bfloat16(0.f);

    // Per-thread, per-tile B-fragment base offsets (constant over K loop).
    int boff[NTILE];
#pragma unroll
    for (int tt = 0; tt < NTILE; tt++) {
        int p = warp * 80 + tt * 8 + grp;        // B-frag column = groupID
        int di = p / 17, dj = p % 17;            // p<=319 -> di<=18 (zero spill rows)
        boff[tt] = (dj & 1) * SPN + di * SW + (dj & ~1) + tig * 2;
    }

    // ldmatrix A lane roles (validated R8 mapping).
    unsigned gshb = (unsigned)__cvta_generic_to_shared(gsh);
    int arow = (lane & 7) + ((lane >> 3) & 1) * 8;
    int akhi = (lane & 16) ? 8 : 0;
    unsigned aoff = (unsigned)(arow * GSE + akhi);

    float acc[NTILE][4];
#pragma unroll
    for (int tt = 0; tt < NTILE; tt++)
#pragma unroll
        for (int k = 0; k < 4; k++) acc[tt][k] = 0.f;

    // ---- cp.async copy of one grd band (16 n x 256 bf16) into ring buf ----
    auto issue_copy = [&](int tb, int buf) {
        int c = tb >> 4, bb = tb & 15;
#pragma unroll
        for (int i = 0; i < 4; i++) {
            int q = t + i * 128;
            int n = q >> 5, ch = q & 31;
            const __nv_bfloat16* src =
                d_grdb + ((size_t)(n * NC + c) * PLANE) + (bb << 8) + (ch << 3);
            unsigned dst = gshb + ((unsigned)buf*BUFE + (unsigned)(n*GSE) + (unsigned)(ch<<3)) * 2u;
            cpasync16(dst, src);
        }
    };

    // prologue: two bands in flight
    issue_copy(tbeg, 0);
    CP_COMMIT();
    if (tbeg + 1 < tend) { issue_copy(tbeg + 1, 1); CP_COMMIT(); }
    int cbuf = 0, ibuf = 2;

    for (int tb = tbeg; tb < tend; tb++) {
        __syncthreads();   // all warps done with band tb-1 compute / satp reads
        if (tb + 2 < tend) {
            issue_copy(tb + 2, ibuf); CP_COMMIT();
            ibuf = (ibuf == NSTAGE-1) ? 0 : ibuf + 1;
        }
        if (tb == tbeg || (tb & 15) == 0) {
            // load sat plane for channel tb>>4 (bf16 source), dual parity
            const __nv_bfloat16* sb = d_satb + (size_t)(m*NC + (tb >> 4)) * PLANE;
            for (int j = t; j < PLANE/2; j += 128) {
                int r = j >> 5, wp = j & 31;
                unsigned v = *(const unsigned*)(sb + r*64 + wp*2);
                *(unsigned*)&sp[(r+8)*SW + wp*2 + 8] = v;
                __nv_bfloat162 bv = *(__nv_bfloat162*)&v;
                sp[SPN + (r+8)*SW + wp*2 + 7] = bv.x;  // odd copy shifted left 1
                sp[SPN + (r+8)*SW + wp*2 + 8] = bv.y;
            }
        }
        int rem = tend - 1 - tb;
        if (rem >= 2) CP_WAIT2(); else if (rem == 1) CP_WAIT1(); else CP_WAIT0();
        __syncthreads();   // band tb data + satp visible to all

        // ---- compute band tb: 16 pipelined steps of 10 mmas ----
        int hb = (tb & 15) << 2;
        int bofft[NTILE];
#pragma unroll
        for (int tt = 0; tt < NTILE; tt++) bofft[tt] = boff[tt] + hb * SW;
        unsigned abb = gshb + ((unsigned)cbuf * BUFE + aoff) * 2u;
        cbuf = (cbuf == NSTAGE-1) ? 0 : cbuf + 1;

        unsigned A0[4], B0[2*NTILE], A1[4], B1[2*NTILE];
        // step s: hh = s>>2 (band row), w0 = (s&3)*16 (k chunk)
        {
            ldsm_x4(A0[0],A0[1],A0[2],A0[3], abb);
#pragma unroll
            for (int tt = 0; tt < NTILE; tt++) {
                const __nv_bfloat16* bp = sp + bofft[tt];
                B0[2*tt]   = *(const unsigned*)bp;
                B0[2*tt+1] = *(const unsigned*)(bp + 8);
            }
        }
#pragma unroll
        for (int u = 0; u < 8; u++) {
            {   // load step 2u+1
                int s = 2*u + 1;
                int hh = s >> 2, w0 = (s & 3) << 4;
                ldsm_x4(A1[0],A1[1],A1[2],A1[3], abb + (unsigned)((hh<<6)+w0)*2u);
                int off = hh * SW + w0;
#pragma unroll
                for (int tt = 0; tt < NTILE; tt++) {
                    const __nv_bfloat16* bp = sp + bofft[tt] + off;
                    B1[2*tt]   = *(const unsigned*)bp;
                    B1[2*tt+1] = *(const unsigned*)(bp + 8);
                }
            }
#pragma unroll
            for (int tt = 0; tt < NTILE; tt++)
                mma16816(acc[tt], A0[0],A0[1],A0[2],A0[3], B0[2*tt], B0[2*tt+1]);
            {   // load step (2u+2) & 15 (wraps to 0 on last pair: harmless reload)
                int s = (2*u + 2) & 15;
                int hh = s >> 2, w0 = (s & 3) << 4;
                ldsm_x4(A0[0],A0[1],A0[2],A0[3], abb + (unsigned)((hh<<6)+w0)*2u);
                int off = hh * SW + w0;
#pragma unroll
                for (int tt = 0; tt < NTILE; tt++) {
                    const __nv_bfloat16* bp = sp + bofft[tt] + off;
                    B0[2*tt]   = *(const unsigned*)bp;
                    B0[2*tt+1] = *(const unsigned*)(bp + 8);
                }
            }
#pragma unroll
            for (int tt = 0; tt < NTILE; tt++)
                mma16816(acc[tt], A1[0],A1[1],A1[2],A1[3], B1[2*tt], B1[2*tt+1]);
        }
    }

    // C layout: c0=C[grp][tig*2], c1=[grp][tig*2+1], c2=[grp+8][tig*2], c3=[grp+8][tig*2+1]
#pragma unroll
    for (int tt = 0; tt < NTILE; tt++) {
        int p0 = warp * 80 + tt * 8 + tig * 2;
        if (p0 < NPOS) {
            atomicAdd(&d_dot[(m * 16 + grp) * NPOS + p0],     acc[tt][0]);
            atomicAdd(&d_dot[(m * 16 + grp + 8) * NPOS + p0], acc[tt][2]);
            if (p0 + 1 < NPOS) {
                atomicAdd(&d_dot[(m * 16 + grp) * NPOS + p0 + 1],     acc[tt][1]);
                atomicAdd(&d_dot[(m * 16 + grp + 8) * NPOS + p0 + 1], acc[tt][3]);
            }
        }
    }
    (void)satf; (void)grdf;
}

// ---------------------------------------------------------------------------
__device__ __forceinline__ float softplusf(float x) {
    return fmaxf(x, 0.f) + log1pf(expf(-fabsf(x)));
}

// Finalize: sim -> dist -> loss terms. One block of 1024 (4 threads per pair).
__global__ void k_final(float* __restrict__ out) {
    __shared__ float invp[NB * NPOS];
    __shared__ float gns[NB];
    __shared__ float dist[NB * NB];
    __shared__ float pos[NB];
    __shared__ float red[256];
    __shared__ float rowmin[NB];
    int t = threadIdx.x;

    for (int i = t; i < NB * NPOS; i += 1024) invp[i] = rsqrtf(d_part[i]);
    if (t < NB) {
        float s = 0.f;
        for (int j = 0; j < 8; j++) s += d_gsqp[t][j];
        gns[t] = sqrtf(s);
    }
    __syncthreads();

    int pair = t >> 2, sub = t & 3;
    int m = pair >> 4, n = pair & 15;
    const float* dp = d_dot + pair * NPOS;
    const float* ip = invp + m * NPOS;
    float best = -3.4e38f;
    for (int k = sub; k < NPOS; k += 4) best = fmaxf(best, dp[k] * ip[k]);
    best = fmaxf(best, __shfl_xor_sync(0xffffffffu, best, 1));
    best = fmaxf(best, __shfl_xor_sync(0xffffffffu, best, 2));
    if (sub == 0) {
        float sim = best / gns[n];
        dist[pair] = 2.f - 2.f * sim;
    }
    __syncthreads();

    if (t < NB) pos[t] = dist[t * NB + t];
    __syncthreads();

    if (t < 256) {
        int mm = t >> 4, nn = t & 15;
        float x1 = (pos[nn] - dist[t]) * 10.f;   // g2s: pos[None,:] - dist
        float x2 = (pos[mm] - dist[t]) * 10.f;   // s2g: pos[:,None] - dist
        red[t] = softplusf(x1) + softplusf(x2);
    }
    if (t < NB) {
        float mn = 3.4e38f;
        for (int k = 0; k < NB; k++) mn = fminf(mn, dist[t * NB + k]);
        rowmin[t] = mn;
    }
    __syncthreads();
    for (int s = 128; s > 0; s >>= 1) {
        if (t < s) red[t] += red[t + s];
        __syncthreads();
    }
    if (t == 0) {
        float pair_n = (float)(NB * (NB - 1));
        float loss = 10.f * (red[0] / (2.f * pair_n));
        float ps = 0.f, ms = 0.f;
        for (int k = 0; k < NB; k++) { ps += pos[k]; ms += rowmin[k]; }
        out[0] = loss;
        out[1] = ps / NB;
        out[2] = ms / NB;
    }
}

// ---------------------------------------------------------------------------
extern "C" void kernel_launch(void* const* d_in, const int* in_sizes, int n_in,
                              void* d_out, int out_size) {
    const float* sat = (const float*)d_in[0];
    const float* grd = (const float*)d_in[1];
    float* out = (float*)d_out;

    // Idempotent attribute set (no allocation; safe inside/outside capture).
    cudaFuncSetAttribute(k_corr_mma,
                         cudaFuncAttributeMaxDynamicSharedMemorySize, SMEM_CORR);

    k_prep<<<dim3(NB, 24), 1024>>>(sat, grd);      // convert + energy/gsq partials + zero
    k_corr_mma<<<dim3(NB, CSPL), 128, SMEM_CORR>>>(sat, grd);
    k_part2<<<NB, 1024>>>();                        // window sums -> d_part
    k_final<<<1, 1024>>>(out);
}